// round 2
// baseline (speedup 1.0000x reference)
#include <cuda_runtime.h>

#define EIN 512
#define H   96
#define BSZ 64
#define QLEN 128
#define PLEN 196

// ---------------- scratch (device globals; no allocations) ----------------
__device__ float g_Q [BSZ*QLEN*H];
__device__ float g_K [BSZ*QLEN*H];
__device__ float g_V [BSZ*QLEN*H];
__device__ float g_tt[BSZ*QLEN*H];   // t_tok projected (then l2-normalized)
__device__ float g_vp[BSZ*PLEN*H];   // v_patch projected (then l2-normalized)
__device__ float g_t [BSZ*H];
__device__ float g_d [BSZ*H];
__device__ float g_v [BSZ*H];

// ---------------- K1: out[M,96] = X[M,512] @ W[96,512]^T + bias ----------------
// block covers 64 rows x 96 cols, 128 threads, micro-tile 8x6
__global__ __launch_bounds__(128) void proj_kernel(
    const float* __restrict__ X, const float* __restrict__ W,
    const float* __restrict__ bias, float* __restrict__ out)
{
    __shared__ float Xs[64*33];
    __shared__ float Ws[96*33];
    int tid = threadIdx.x;
    int tm = tid >> 4, tn = tid & 15;   // 8 x 16 thread grid
    int m0 = tm*8,  n0 = tn*6;
    long mb = blockIdx.x;
    const float* Xb = X + mb*64*EIN;

    float acc[8][6];
#pragma unroll
    for (int i=0;i<8;i++)
#pragma unroll
        for (int j=0;j<6;j++) acc[i][j]=0.f;

    for (int k0=0;k0<EIN;k0+=32) {
        __syncthreads();
        for (int idx=tid; idx<64*32; idx+=128) {
            int m = idx>>5, kk = idx&31;
            Xs[m*33+kk] = Xb[m*EIN + k0 + kk];
        }
        for (int idx=tid; idx<96*32; idx+=128) {
            int n = idx>>5, kk = idx&31;
            Ws[n*33+kk] = W[n*EIN + k0 + kk];
        }
        __syncthreads();
#pragma unroll 4
        for (int kk=0;kk<32;kk++) {
            float a[8], b[6];
#pragma unroll
            for (int i=0;i<8;i++) a[i]=Xs[(m0+i)*33+kk];
#pragma unroll
            for (int j=0;j<6;j++) b[j]=Ws[(n0+j)*33+kk];
#pragma unroll
            for (int i=0;i<8;i++)
#pragma unroll
                for (int j=0;j<6;j++) acc[i][j] += a[i]*b[j];
        }
    }
#pragma unroll
    for (int i=0;i<8;i++)
#pragma unroll
        for (int j=0;j<6;j++)
            out[(mb*64+m0+i)*H + n0 + j] = acc[i][j] + bias[n0+j];
}

// ---------------- K1b: in-place row l2-normalize (rows of 96) ----------------
__global__ void l2n_kernel(float* __restrict__ x, int rows)
{
    int warp = (blockIdx.x*blockDim.x + threadIdx.x) >> 5;
    int lane = threadIdx.x & 31;
    if (warp >= rows) return;
    float* r = x + (long)warp*H;
    float x0=r[lane], x1=r[lane+32], x2=r[lane+64];
    float ss = x0*x0 + x1*x1 + x2*x2;
#pragma unroll
    for (int o=16;o;o>>=1) ss += __shfl_xor_sync(0xffffffffu, ss, o);
    float sc = 1.f / fmaxf(sqrtf(ss), 1e-6f);
    r[lane]=x0*sc; r[lane+32]=x1*sc; r[lane+64]=x2*sc;
}

// ---------------- K2: out[i,j] = 0.5*( t[i].d[j] + t[i].v[j] ) ----------------
__global__ void gg_kernel(float* __restrict__ out)
{
    int i = blockIdx.x, j = threadIdx.x;
    const float* ti = g_t + i*H;
    const float* dj = g_d + j*H;
    const float* vj = g_v + j*H;
    float s = 0.f;
#pragma unroll 8
    for (int h=0;h<H;h++) s += ti[h]*(dj[h]+vj[h]);
    out[i*64+j] = 0.5f*s;
}

// ---------------- K3: TGL per pair (b,c) ----------------
// scores = Q[b](128x96) @ K[c]^T -> softmax rows -> w = mean_q attn ->
// ctx = w.V[c] -> LN -> l2n -> dot with d[b] ; out += 0.5*val
#define SQS 97
__global__ __launch_bounds__(256,2) void tgl_kernel(
    const float* __restrict__ lng, const float* __restrict__ lnb,
    float* __restrict__ out)
{
    extern __shared__ float sm[];
    float* Qs = sm;               // [128][97]
    float* Ks = sm + 128*SQS;     // [128][97]
    float* Ss = sm;               // alias: [128][128], valid after GEMM
    float* Vs = sm;               // alias: [128][96],  valid after w computed
    float* invden = sm + 2*128*SQS;   // [128]
    float* wv     = invden + 128;     // [128]
    float* ctxs   = wv + 128;         // [96]

    int tid = threadIdx.x;
    int b = blockIdx.y, c = blockIdx.x;
    int tm = tid >> 4, tn = tid & 15;   // 16 x 16
    int m0 = tm*8;

    const float* Qg = g_Q + (long)b*QLEN*H;
    const float* Kg = g_K + (long)c*QLEN*H;

    // load Q,K into padded-stride smem (coalesced global, conflict-free STS)
    for (int idx=tid; idx<128*24; idx+=256) {
        int q = idx/24; int h4 = (idx%24)*4;
        float4 a = *(const float4*)(Qg + q*H + h4);
        float* dq = Qs + q*SQS + h4;
        dq[0]=a.x; dq[1]=a.y; dq[2]=a.z; dq[3]=a.w;
        float4 k = *(const float4*)(Kg + q*H + h4);
        float* dk = Ks + q*SQS + h4;
        dk[0]=k.x; dk[1]=k.y; dk[2]=k.z; dk[3]=k.w;
    }
    __syncthreads();

    float acc[8][8];
#pragma unroll
    for (int i=0;i<8;i++)
#pragma unroll
        for (int j=0;j<8;j++) acc[i][j]=0.f;

#pragma unroll 2
    for (int h=0;h<H;h++) {
        float a[8], bb[8];
#pragma unroll
        for (int i=0;i<8;i++) a[i]  = Qs[(m0+i)*SQS + h];
#pragma unroll
        for (int j=0;j<8;j++) bb[j] = Ks[(j*16+tn)*SQS + h];
#pragma unroll
        for (int i=0;i<8;i++)
#pragma unroll
            for (int j=0;j<8;j++) acc[i][j] += a[i]*bb[j];
    }
    __syncthreads();   // all Qs/Ks reads done; safe to overwrite with Ss

    const float SC = 0.1020620726159658f;  // 1/sqrt(96)
#pragma unroll
    for (int i=0;i<8;i++)
#pragma unroll
        for (int j=0;j<8;j++)
            Ss[(m0+i)*128 + j*16 + tn] = acc[i][j]*SC;
    __syncthreads();

    // row softmax: 8 warps x 16 rows; store exp in place, 1/denom per row
    {
        int w = tid>>5, lane = tid&31;
        for (int r=0;r<16;r++) {
            int row = w*16 + r;
            float* Sr = Ss + row*128;
            float v0=Sr[lane], v1=Sr[lane+32], v2=Sr[lane+64], v3=Sr[lane+96];
            float m = fmaxf(fmaxf(v0,v1), fmaxf(v2,v3));
#pragma unroll
            for (int o=16;o;o>>=1) m = fmaxf(m, __shfl_xor_sync(0xffffffffu,m,o));
            float e0=__expf(v0-m), e1=__expf(v1-m), e2=__expf(v2-m), e3=__expf(v3-m);
            float s = e0+e1+e2+e3;
#pragma unroll
            for (int o=16;o;o>>=1) s += __shfl_xor_sync(0xffffffffu,s,o);
            Sr[lane]=e0; Sr[lane+32]=e1; Sr[lane+64]=e2; Sr[lane+96]=e3;
            if (lane==0) invden[row] = 1.f/s;
        }
    }
    __syncthreads();

    // column pass: w[k] = (1/128) sum_q exp[q,k] * invden[q]
    if (tid < 128) {
        float s = 0.f;
#pragma unroll 4
        for (int q=0;q<128;q++) s += Ss[q*128 + tid] * invden[q];
        wv[tid] = s * (1.f/128.f);
    }
    __syncthreads();   // Ss dead; load V over it

    {
        const float* Vg = g_V + (long)c*QLEN*H;
        for (int idx=tid; idx<128*24; idx+=256)
            ((float4*)Vs)[idx] = ((const float4*)Vg)[idx];
    }
    __syncthreads();

    // context[h] = sum_k w[k]*V[k][h]
    if (tid < 96) {
        float s = 0.f;
#pragma unroll 4
        for (int k=0;k<128;k++) s += wv[k]*Vs[k*H + tid];
        ctxs[tid] = s;
    }
    __syncthreads();

    // LayerNorm + l2n + dot(d[b]) on warp 0
    if (tid < 32) {
        float x0=ctxs[tid], x1=ctxs[tid+32], x2=ctxs[tid+64];
        float mu = x0+x1+x2;
#pragma unroll
        for (int o=16;o;o>>=1) mu += __shfl_xor_sync(0xffffffffu,mu,o);
        mu *= (1.f/96.f);
        float d0=x0-mu, d1=x1-mu, d2=x2-mu;
        float var = d0*d0 + d1*d1 + d2*d2;
#pragma unroll
        for (int o=16;o;o>>=1) var += __shfl_xor_sync(0xffffffffu,var,o);
        var *= (1.f/96.f);
        float rstd = rsqrtf(var + 1e-5f);
        float n0 = d0*rstd*lng[tid]    + lnb[tid];
        float n1 = d1*rstd*lng[tid+32] + lnb[tid+32];
        float n2 = d2*rstd*lng[tid+64] + lnb[tid+64];
        float ss = n0*n0 + n1*n1 + n2*n2;
#pragma unroll
        for (int o=16;o;o>>=1) ss += __shfl_xor_sync(0xffffffffu,ss,o);
        float sc = 1.f / fmaxf(sqrtf(ss), 1e-6f);
        const float* db = g_d + b*H;
        float dt = db[tid]*n0 + db[tid+32]*n1 + db[tid+64]*n2;
#pragma unroll
        for (int o=16;o;o>>=1) dt += __shfl_xor_sync(0xffffffffu,dt,o);
        if (tid==0) out[b*64+c] += 0.5f * (dt*sc);
    }
}

// ---------------- K4: CLL per pair (b,c): max over t_tok[b] @ v_pat[c]^T ----------------
// 448 threads = 16(tm) x 28(tn), micro 8x7 covers 128x196 exactly
__global__ __launch_bounds__(448,1) void cll_kernel(float* __restrict__ out)
{
    extern __shared__ float sm[];
    float* As  = sm;                 // [128][96] natural (broadcast reads)
    float* Bs  = sm + 128*H;         // [196][33] padded chunk of 32 h
    float* red = Bs + 196*33;        // [14]

    int tid = threadIdx.x;
    int b = blockIdx.y, c = blockIdx.x;
    int tm = tid/28, tn = tid%28;
    int m0 = tm*8,  n0 = tn*7;

    const float* Ag = g_tt + (long)b*QLEN*H;
    const float* Bg = g_vp + (long)c*PLEN*H;

    float acc[8][7];
#pragma unroll
    for (int i=0;i<8;i++)
#pragma unroll
        for (int j=0;j<7;j++) acc[i][j]=0.f;

    for (int h0=0; h0<H; h0+=32) {
        __syncthreads();
        if (h0==0) {
            for (int idx=tid; idx<128*24; idx+=448)
                ((float4*)As)[idx] = ((const float4*)Ag)[idx];
        }
        for (int idx=tid; idx<196*32; idx+=448) {
            int p = idx>>5, hh = idx&31;
            Bs[p*33+hh] = Bg[p*H + h0 + hh];
        }
        __syncthreads();
#pragma unroll 2
        for (int hh=0; hh<32; hh++) {
            float a[8], bb[7];
#pragma unroll
            for (int i=0;i<8;i++) a[i]  = As[(m0+i)*H + h0 + hh];
#pragma unroll
            for (int j=0;j<7;j++) bb[j] = Bs[(n0+j)*33 + hh];
#pragma unroll
            for (int i=0;i<8;i++)
#pragma unroll
                for (int j=0;j<7;j++) acc[i][j] += a[i]*bb[j];
        }
    }

    float m = -1e30f;
#pragma unroll
    for (int i=0;i<8;i++)
#pragma unroll
        for (int j=0;j<7;j++) m = fmaxf(m, acc[i][j]);
#pragma unroll
    for (int o=16;o;o>>=1) m = fmaxf(m, __shfl_xor_sync(0xffffffffu,m,o));
    if ((tid&31)==0) red[tid>>5] = m;
    __syncthreads();
    if (tid==0) {
        float mm = red[0];
#pragma unroll
        for (int w=1;w<14;w++) mm = fmaxf(mm, red[w]);
        out[b*64+c] += 0.5f*mm;
    }
}

// ---------------- host ----------------
extern "C" void kernel_launch(void* const* d_in, const int* in_sizes, int n_in,
                              void* d_out, int out_size)
{
    const float* z_d_cls = (const float*)d_in[0];
    const float* Z_d_tok = (const float*)d_in[1];
    const float* z_t_cls = (const float*)d_in[2];
    const float* Z_t_tok = (const float*)d_in[3];
    const float* z_v_cls = (const float*)d_in[4];
    const float* Z_v_pat = (const float*)d_in[5];
    const float *W_t_cls=(const float*)d_in[6],  *b_t_cls=(const float*)d_in[7];
    const float *W_d_cls=(const float*)d_in[8],  *b_d_cls=(const float*)d_in[9];
    const float *W_v_cls=(const float*)d_in[10], *b_v_cls=(const float*)d_in[11];
    const float *W_t_tok=(const float*)d_in[12], *b_t_tok=(const float*)d_in[13];
    const float *W_v_pat=(const float*)d_in[14], *b_v_pat=(const float*)d_in[15];
    const float *W_q=(const float*)d_in[16], *b_q=(const float*)d_in[17];
    const float *W_k=(const float*)d_in[18], *b_k=(const float*)d_in[19];
    const float *W_v=(const float*)d_in[20], *b_v=(const float*)d_in[21];
    const float *ln_g=(const float*)d_in[22], *ln_b=(const float*)d_in[23];
    float* out = (float*)d_out;

    float *Qp,*Kp,*Vp,*ttp,*vpp,*tp,*dp,*vp;
    cudaGetSymbolAddress((void**)&Qp,  g_Q);
    cudaGetSymbolAddress((void**)&Kp,  g_K);
    cudaGetSymbolAddress((void**)&Vp,  g_V);
    cudaGetSymbolAddress((void**)&ttp, g_tt);
    cudaGetSymbolAddress((void**)&vpp, g_vp);
    cudaGetSymbolAddress((void**)&tp,  g_t);
    cudaGetSymbolAddress((void**)&dp,  g_d);
    cudaGetSymbolAddress((void**)&vp,  g_v);

    const int SM3 = (2*128*SQS + 128 + 128 + 96) * (int)sizeof(float);   // ~100.7 KB
    const int SM4 = (128*H + 196*33 + 16) * (int)sizeof(float);          // ~75.1 KB
    cudaFuncSetAttribute(tgl_kernel, cudaFuncAttributeMaxDynamicSharedMemorySize, SM3);
    cudaFuncSetAttribute(cll_kernel, cudaFuncAttributeMaxDynamicSharedMemorySize, SM4);

    // projections
    proj_kernel<<<128,128>>>(Z_d_tok, W_q,      b_q,      Qp);
    proj_kernel<<<128,128>>>(Z_t_tok, W_k,      b_k,      Kp);
    proj_kernel<<<128,128>>>(Z_t_tok, W_v,      b_v,      Vp);
    proj_kernel<<<128,128>>>(Z_t_tok, W_t_tok,  b_t_tok,  ttp);
    proj_kernel<<<196,128>>>(Z_v_pat, W_v_pat,  b_v_pat,  vpp);
    proj_kernel<<<1,  128>>>(z_t_cls, W_t_cls,  b_t_cls,  tp);
    proj_kernel<<<1,  128>>>(z_d_cls, W_d_cls,  b_d_cls,  dp);
    proj_kernel<<<1,  128>>>(z_v_cls, W_v_cls,  b_v_cls,  vp);

    // normalizations
    l2n_kernel<<<(BSZ*QLEN*32+255)/256,256>>>(ttp, BSZ*QLEN);
    l2n_kernel<<<(BSZ*PLEN*32+255)/256,256>>>(vpp, BSZ*PLEN);
    l2n_kernel<<<8,256>>>(tp, BSZ);
    l2n_kernel<<<8,256>>>(dp, BSZ);
    l2n_kernel<<<8,256>>>(vp, BSZ);

    // out = 0.5*(S_TGG + S_CGG)
    gg_kernel<<<64,64>>>(out);
    // out += 0.5*S_TGL
    tgl_kernel<<<dim3(64,64),256,SM3>>>(ln_g, ln_b, out);
    // out += 0.5*S_CLL
    cll_kernel<<<dim3(64,64),448,SM4>>>(out);
}

// round 3
// speedup vs baseline: 1.2733x; 1.2733x over previous
#include <cuda_runtime.h>

#define EIN 512
#define H   96
#define BSZ 64
#define QLEN 128
#define PLEN 196

// ---------------- scratch (device globals; no allocations) ----------------
__device__ float g_Q [BSZ*QLEN*H];
__device__ float g_K [BSZ*QLEN*H];
__device__ float g_V [BSZ*QLEN*H];
__device__ float g_tt[BSZ*QLEN*H];   // t_tok projected + l2-normalized
__device__ float g_vp[BSZ*PLEN*H];   // v_patch projected + l2-normalized
__device__ float g_t [BSZ*H];
__device__ float g_d [BSZ*H];
__device__ float g_v [BSZ*H];

// ---------------- K1: batched projection ----------------
// One launch for all 8 projections. Each block computes a 64-row x 96-col
// output tile of out = X @ W^T + b, optionally l2-normalizing rows (len 96).
struct ProjArgs {
    const float* X[8];
    const float* W[8];
    const float* Bv[8];
    float*       Out[8];
    int          tile_start[9];  // cumulative 64-row tiles
    int          l2n[8];
};

__global__ __launch_bounds__(256) void proj_all(ProjArgs pa)
{
    __shared__ float Xs[64*33];
    __shared__ float Ws[96*33];

    int bid = blockIdx.x;
    int mi = 0;
#pragma unroll
    for (int i=1;i<8;i++) if (bid >= pa.tile_start[i]) mi = i;
    int tile = bid - pa.tile_start[mi];

    const float* Xb   = pa.X[mi] + (long)tile*64*EIN;
    const float* W    = pa.W[mi];
    const float* bias = pa.Bv[mi];
    float*       out  = pa.Out[mi] + (long)tile*64*H;

    int tid = threadIdx.x;
    int tm = tid >> 4, tn = tid & 15;     // 16 x 16 threads
    int m0 = tm*4,  n0 = tn*6;            // micro-tile 4x6

    float acc[4][6];
#pragma unroll
    for (int i=0;i<4;i++)
#pragma unroll
        for (int j=0;j<6;j++) acc[i][j]=0.f;

    for (int k0=0;k0<EIN;k0+=32) {
        __syncthreads();
        for (int idx=tid; idx<64*32; idx+=256) {
            int m = idx>>5, kk = idx&31;
            Xs[m*33+kk] = Xb[m*EIN + k0 + kk];
        }
        for (int idx=tid; idx<96*32; idx+=256) {
            int n = idx>>5, kk = idx&31;
            Ws[n*33+kk] = W[n*EIN + k0 + kk];
        }
        __syncthreads();
#pragma unroll 8
        for (int kk=0;kk<32;kk++) {
            float a[4], b[6];
#pragma unroll
            for (int i=0;i<4;i++) a[i]=Xs[(m0+i)*33+kk];
#pragma unroll
            for (int j=0;j<6;j++) b[j]=Ws[(n0+j)*33+kk];
#pragma unroll
            for (int i=0;i<4;i++)
#pragma unroll
                for (int j=0;j<6;j++) acc[i][j] += a[i]*b[j];
        }
    }

#pragma unroll
    for (int i=0;i<4;i++)
#pragma unroll
        for (int j=0;j<6;j++) acc[i][j] += bias[n0+j];

    if (pa.l2n[mi]) {
        __syncthreads();
#pragma unroll
        for (int i=0;i<4;i++) {
            float ss = 0.f;
#pragma unroll
            for (int j=0;j<6;j++) ss += acc[i][j]*acc[i][j];
            Xs[(m0+i)*17 + tn] = ss;
        }
        __syncthreads();
        if (tid < 64) {
            float s = 0.f;
#pragma unroll
            for (int t=0;t<16;t++) s += Xs[tid*17+t];
            Ws[tid] = 1.f / fmaxf(sqrtf(s), 1e-6f);
        }
        __syncthreads();
#pragma unroll
        for (int i=0;i<4;i++) {
            float sc = Ws[m0+i];
#pragma unroll
            for (int j=0;j<6;j++) acc[i][j] *= sc;
        }
    }

#pragma unroll
    for (int i=0;i<4;i++)
#pragma unroll
        for (int j=0;j<6;j++)
            out[(m0+i)*H + n0 + j] = acc[i][j];
}

// ---------------- K2: out[i,j] = 0.5*( t[i].d[j] + t[i].v[j] ) ----------------
__global__ void gg_kernel(float* __restrict__ out)
{
    int i = blockIdx.x, j = threadIdx.x;
    const float* ti = g_t + i*H;
    const float* dj = g_d + j*H;
    const float* vj = g_v + j*H;
    float s = 0.f;
#pragma unroll 8
    for (int h=0;h<H;h++) s += ti[h]*(dj[h]+vj[h]);
    out[i*64+j] = 0.5f*s;
}

// ---------------- K3: TGL per pair (b,c) ----------------
// scores = Q[b](128x96) @ K[c]^T -> softmax rows -> w = mean_q attn ->
// ctx = w.V[c] -> LN -> l2n -> dot with d[b] ; out += 0.5*val
#define SQS 97
__global__ __launch_bounds__(256,2) void tgl_kernel(
    const float* __restrict__ lng, const float* __restrict__ lnb,
    float* __restrict__ out)
{
    extern __shared__ float sm[];
    float* Qs = sm;               // [128][97]
    float* Ks = sm + 128*SQS;     // [128][97]
    float* Ss = sm;               // alias: [128][128], valid after GEMM
    float* Vs = sm;               // alias: [128][96],  valid after w computed
    float* invden = sm + 2*128*SQS;   // [128]
    float* wv     = invden + 128;     // [128]
    float* ctxs   = wv + 128;         // [96]

    int tid = threadIdx.x;
    int b = blockIdx.y, c = blockIdx.x;
    int tm = tid >> 4, tn = tid & 15;   // 16 x 16
    int m0 = tm*8;

    const float* Qg = g_Q + (long)b*QLEN*H;
    const float* Kg = g_K + (long)c*QLEN*H;

    for (int idx=tid; idx<128*24; idx+=256) {
        int q = idx/24; int h4 = (idx%24)*4;
        float4 a = *(const float4*)(Qg + q*H + h4);
        float* dq = Qs + q*SQS + h4;
        dq[0]=a.x; dq[1]=a.y; dq[2]=a.z; dq[3]=a.w;
        float4 k = *(const float4*)(Kg + q*H + h4);
        float* dk = Ks + q*SQS + h4;
        dk[0]=k.x; dk[1]=k.y; dk[2]=k.z; dk[3]=k.w;
    }
    __syncthreads();

    float acc[8][8];
#pragma unroll
    for (int i=0;i<8;i++)
#pragma unroll
        for (int j=0;j<8;j++) acc[i][j]=0.f;

#pragma unroll 2
    for (int h=0;h<H;h++) {
        float a[8], bb[8];
#pragma unroll
        for (int i=0;i<8;i++) a[i]  = Qs[(m0+i)*SQS + h];
#pragma unroll
        for (int j=0;j<8;j++) bb[j] = Ks[(j*16+tn)*SQS + h];
#pragma unroll
        for (int i=0;i<8;i++)
#pragma unroll
            for (int j=0;j<8;j++) acc[i][j] += a[i]*bb[j];
    }
    __syncthreads();

    const float SC = 0.1020620726159658f;  // 1/sqrt(96)
#pragma unroll
    for (int i=0;i<8;i++)
#pragma unroll
        for (int j=0;j<8;j++)
            Ss[(m0+i)*128 + j*16 + tn] = acc[i][j]*SC;
    __syncthreads();

    {
        int w = tid>>5, lane = tid&31;
        for (int r=0;r<16;r++) {
            int row = w*16 + r;
            float* Sr = Ss + row*128;
            float v0=Sr[lane], v1=Sr[lane+32], v2=Sr[lane+64], v3=Sr[lane+96];
            float m = fmaxf(fmaxf(v0,v1), fmaxf(v2,v3));
#pragma unroll
            for (int o=16;o;o>>=1) m = fmaxf(m, __shfl_xor_sync(0xffffffffu,m,o));
            float e0=__expf(v0-m), e1=__expf(v1-m), e2=__expf(v2-m), e3=__expf(v3-m);
            float s = e0+e1+e2+e3;
#pragma unroll
            for (int o=16;o;o>>=1) s += __shfl_xor_sync(0xffffffffu,s,o);
            Sr[lane]=e0; Sr[lane+32]=e1; Sr[lane+64]=e2; Sr[lane+96]=e3;
            if (lane==0) invden[row] = 1.f/s;
        }
    }
    __syncthreads();

    if (tid < 128) {
        float s = 0.f;
#pragma unroll 4
        for (int q=0;q<128;q++) s += Ss[q*128 + tid] * invden[q];
        wv[tid] = s * (1.f/128.f);
    }
    __syncthreads();

    {
        const float* Vg = g_V + (long)c*QLEN*H;
        for (int idx=tid; idx<128*24; idx+=256)
            ((float4*)Vs)[idx] = ((const float4*)Vg)[idx];
    }
    __syncthreads();

    if (tid < 96) {
        float s = 0.f;
#pragma unroll 4
        for (int k=0;k<128;k++) s += wv[k]*Vs[k*H + tid];
        ctxs[tid] = s;
    }
    __syncthreads();

    if (tid < 32) {
        float x0=ctxs[tid], x1=ctxs[tid+32], x2=ctxs[tid+64];
        float mu = x0+x1+x2;
#pragma unroll
        for (int o=16;o;o>>=1) mu += __shfl_xor_sync(0xffffffffu,mu,o);
        mu *= (1.f/96.f);
        float d0=x0-mu, d1=x1-mu, d2=x2-mu;
        float var = d0*d0 + d1*d1 + d2*d2;
#pragma unroll
        for (int o=16;o;o>>=1) var += __shfl_xor_sync(0xffffffffu,var,o);
        var *= (1.f/96.f);
        float rstd = rsqrtf(var + 1e-5f);
        float n0 = d0*rstd*lng[tid]    + lnb[tid];
        float n1 = d1*rstd*lng[tid+32] + lnb[tid+32];
        float n2 = d2*rstd*lng[tid+64] + lnb[tid+64];
        float ss = n0*n0 + n1*n1 + n2*n2;
#pragma unroll
        for (int o=16;o;o>>=1) ss += __shfl_xor_sync(0xffffffffu,ss,o);
        float sc = 1.f / fmaxf(sqrtf(ss), 1e-6f);
        const float* db = g_d + b*H;
        float dt = db[tid]*n0 + db[tid+32]*n1 + db[tid+64]*n2;
#pragma unroll
        for (int o=16;o;o>>=1) dt += __shfl_xor_sync(0xffffffffu,dt,o);
        if (tid==0) out[b*64+c] += 0.5f * (dt*sc);
    }
}

// ---------------- K4: CLL per pair (b,c) ----------------
__global__ __launch_bounds__(448,1) void cll_kernel(float* __restrict__ out)
{
    extern __shared__ float sm[];
    float* As  = sm;                 // [128][96] natural (broadcast reads)
    float* Bs  = sm + 128*H;         // [196][33] padded chunk of 32 h
    float* red = Bs + 196*33;        // [14]

    int tid = threadIdx.x;
    int b = blockIdx.y, c = blockIdx.x;
    int tm = tid/28, tn = tid%28;
    int m0 = tm*8,  n0 = tn*7;

    const float* Ag = g_tt + (long)b*QLEN*H;
    const float* Bg = g_vp + (long)c*PLEN*H;

    float acc[8][7];
#pragma unroll
    for (int i=0;i<8;i++)
#pragma unroll
        for (int j=0;j<7;j++) acc[i][j]=0.f;

    for (int h0=0; h0<H; h0+=32) {
        __syncthreads();
        if (h0==0) {
            for (int idx=tid; idx<128*24; idx+=448)
                ((float4*)As)[idx] = ((const float4*)Ag)[idx];
        }
        for (int idx=tid; idx<196*32; idx+=448) {
            int p = idx>>5, hh = idx&31;
            Bs[p*33+hh] = Bg[p*H + h0 + hh];
        }
        __syncthreads();
#pragma unroll 2
        for (int hh=0; hh<32; hh++) {
            float a[8], bb[7];
#pragma unroll
            for (int i=0;i<8;i++) a[i]  = As[(m0+i)*H + h0 + hh];
#pragma unroll
            for (int j=0;j<7;j++) bb[j] = Bs[(n0+j)*33 + hh];
#pragma unroll
            for (int i=0;i<8;i++)
#pragma unroll
                for (int j=0;j<7;j++) acc[i][j] += a[i]*bb[j];
        }
    }

    float m = -1e30f;
#pragma unroll
    for (int i=0;i<8;i++)
#pragma unroll
        for (int j=0;j<7;j++) m = fmaxf(m, acc[i][j]);
#pragma unroll
    for (int o=16;o;o>>=1) m = fmaxf(m, __shfl_xor_sync(0xffffffffu,m,o));
    if ((tid&31)==0) red[tid>>5] = m;
    __syncthreads();
    if (tid==0) {
        float mm = red[0];
#pragma unroll
        for (int w=1;w<14;w++) mm = fmaxf(mm, red[w]);
        out[b*64+c] += 0.5f*mm;
    }
}

// ---------------- host ----------------
extern "C" void kernel_launch(void* const* d_in, const int* in_sizes, int n_in,
                              void* d_out, int out_size)
{
    const float* z_d_cls = (const float*)d_in[0];
    const float* Z_d_tok = (const float*)d_in[1];
    const float* z_t_cls = (const float*)d_in[2];
    const float* Z_t_tok = (const float*)d_in[3];
    const float* z_v_cls = (const float*)d_in[4];
    const float* Z_v_pat = (const float*)d_in[5];
    const float *W_t_cls=(const float*)d_in[6],  *b_t_cls=(const float*)d_in[7];
    const float *W_d_cls=(const float*)d_in[8],  *b_d_cls=(const float*)d_in[9];
    const float *W_v_cls=(const float*)d_in[10], *b_v_cls=(const float*)d_in[11];
    const float *W_t_tok=(const float*)d_in[12], *b_t_tok=(const float*)d_in[13];
    const float *W_v_pat=(const float*)d_in[14], *b_v_pat=(const float*)d_in[15];
    const float *W_q=(const float*)d_in[16], *b_q=(const float*)d_in[17];
    const float *W_k=(const float*)d_in[18], *b_k=(const float*)d_in[19];
    const float *W_v=(const float*)d_in[20], *b_v=(const float*)d_in[21];
    const float *ln_g=(const float*)d_in[22], *ln_b=(const float*)d_in[23];
    float* out = (float*)d_out;

    float *Qp,*Kp,*Vp,*ttp,*vpp,*tp,*dp,*vp;
    cudaGetSymbolAddress((void**)&Qp,  g_Q);
    cudaGetSymbolAddress((void**)&Kp,  g_K);
    cudaGetSymbolAddress((void**)&Vp,  g_V);
    cudaGetSymbolAddress((void**)&ttp, g_tt);
    cudaGetSymbolAddress((void**)&vpp, g_vp);
    cudaGetSymbolAddress((void**)&tp,  g_t);
    cudaGetSymbolAddress((void**)&dp,  g_d);
    cudaGetSymbolAddress((void**)&vp,  g_v);

    const int SM3 = (2*128*SQS + 128 + 128 + 96) * (int)sizeof(float);   // ~100.7 KB
    const int SM4 = (128*H + 196*33 + 16) * (int)sizeof(float);          // ~75.1 KB
    cudaFuncSetAttribute(tgl_kernel, cudaFuncAttributeMaxDynamicSharedMemorySize, SM3);
    cudaFuncSetAttribute(cll_kernel, cudaFuncAttributeMaxDynamicSharedMemorySize, SM4);

    // ---- one batched projection launch (all 8 matrices, fused l2n) ----
    ProjArgs pa;
    pa.X[0]=Z_d_tok; pa.W[0]=W_q;     pa.Bv[0]=b_q;     pa.Out[0]=Qp;  pa.l2n[0]=0;
    pa.X[1]=Z_t_tok; pa.W[1]=W_k;     pa.Bv[1]=b_k;     pa.Out[1]=Kp;  pa.l2n[1]=0;
    pa.X[2]=Z_t_tok; pa.W[2]=W_v;     pa.Bv[2]=b_v;     pa.Out[2]=Vp;  pa.l2n[2]=0;
    pa.X[3]=Z_t_tok; pa.W[3]=W_t_tok; pa.Bv[3]=b_t_tok; pa.Out[3]=ttp; pa.l2n[3]=1;
    pa.X[4]=Z_v_pat; pa.W[4]=W_v_pat; pa.Bv[4]=b_v_pat; pa.Out[4]=vpp; pa.l2n[4]=1;
    pa.X[5]=z_t_cls; pa.W[5]=W_t_cls; pa.Bv[5]=b_t_cls; pa.Out[5]=tp;  pa.l2n[5]=1;
    pa.X[6]=z_d_cls; pa.W[6]=W_d_cls; pa.Bv[6]=b_d_cls; pa.Out[6]=dp;  pa.l2n[6]=1;
    pa.X[7]=z_v_cls; pa.W[7]=W_v_cls; pa.Bv[7]=b_v_cls; pa.Out[7]=vp;  pa.l2n[7]=1;
    int nt[8] = {128,128,128,128,196,1,1,1};
    pa.tile_start[0]=0;
    for (int i=0;i<8;i++) pa.tile_start[i+1]=pa.tile_start[i]+nt[i];

    proj_all<<<pa.tile_start[8],256>>>(pa);

    // out = 0.5*(S_TGG + S_CGG)
    gg_kernel<<<64,64>>>(out);
    // out += 0.5*S_TGL
    tgl_kernel<<<dim3(64,64),256,SM3>>>(ln_g, ln_b, out);
    // out += 0.5*S_CLL
    cll_kernel<<<dim3(64,64),448,SM4>>>(out);
}

// round 4
// speedup vs baseline: 1.3794x; 1.0833x over previous
#include <cuda_runtime.h>

#define EIN 512
#define H   96
#define BSZ 64
#define QLEN 128
#define PLEN 196
#define PPAD 224

// ---------------- scratch (device globals; transposed h-major layouts) ----------------
__device__ float g_Qt [BSZ*H*QLEN];   // [b][h][q]
__device__ float g_Kt [BSZ*H*QLEN];
__device__ float g_Vt [BSZ*H*QLEN];
__device__ float g_ttt[BSZ*H*QLEN];   // t_tok, l2-normalized, [b][h][t]
__device__ float g_vpt[BSZ*H*PLEN];   // v_patch, l2-normalized, [c][h][p]
__device__ float g_t [BSZ*H];
__device__ float g_d [BSZ*H];
__device__ float g_v [BSZ*H];

// ---------------- K1: batched projection (all 8), optional l2n, optional transpose ----------------
struct ProjArgs {
    const float* X[8];
    const float* W[8];
    const float* Bv[8];
    float*       Out[8];
    int          tile_start[9];
    int          l2n[8];
    int          L[8];      // >0: write transposed [row/L][96][L]; 0: row-major [row][96]
};

__global__ __launch_bounds__(256) void proj_all(ProjArgs pa)
{
    __shared__ float Xs[64*33];
    __shared__ float Ws[96*33];

    int bid = blockIdx.x;
    int mi = 0;
#pragma unroll
    for (int i=1;i<8;i++) if (bid >= pa.tile_start[i]) mi = i;
    int tile = bid - pa.tile_start[mi];

    const float* Xb   = pa.X[mi] + (long)tile*64*EIN;
    const float* W    = pa.W[mi];
    const float* bias = pa.Bv[mi];

    int tid = threadIdx.x;
    int tm = tid >> 4, tn = tid & 15;     // 16 x 16 threads
    int m0 = tm*4,  n0 = tn*6;            // micro-tile 4x6

    float acc[4][6];
#pragma unroll
    for (int i=0;i<4;i++)
#pragma unroll
        for (int j=0;j<6;j++) acc[i][j]=0.f;

    for (int k0=0;k0<EIN;k0+=32) {
        __syncthreads();
        for (int idx=tid; idx<64*32; idx+=256) {
            int m = idx>>5, kk = idx&31;
            Xs[m*33+kk] = Xb[m*EIN + k0 + kk];
        }
        for (int idx=tid; idx<96*32; idx+=256) {
            int n = idx>>5, kk = idx&31;
            Ws[n*33+kk] = W[n*EIN + k0 + kk];
        }
        __syncthreads();
#pragma unroll 8
        for (int kk=0;kk<32;kk++) {
            float a[4], b[6];
#pragma unroll
            for (int i=0;i<4;i++) a[i]=Xs[(m0+i)*33+kk];
#pragma unroll
            for (int j=0;j<6;j++) b[j]=Ws[(n0+j)*33+kk];
#pragma unroll
            for (int i=0;i<4;i++)
#pragma unroll
                for (int j=0;j<6;j++) acc[i][j] += a[i]*b[j];
        }
    }

#pragma unroll
    for (int i=0;i<4;i++)
#pragma unroll
        for (int j=0;j<6;j++) acc[i][j] += bias[n0+j];

    if (pa.l2n[mi]) {
        __syncthreads();
#pragma unroll
        for (int i=0;i<4;i++) {
            float ss = 0.f;
#pragma unroll
            for (int j=0;j<6;j++) ss += acc[i][j]*acc[i][j];
            Xs[(m0+i)*17 + tn] = ss;
        }
        __syncthreads();
        if (tid < 64) {
            float s = 0.f;
#pragma unroll
            for (int t=0;t<16;t++) s += Xs[tid*17+t];
            Ws[tid] = 1.f / fmaxf(sqrtf(s), 1e-6f);
        }
        __syncthreads();
#pragma unroll
        for (int i=0;i<4;i++) {
            float sc = Ws[m0+i];
#pragma unroll
            for (int j=0;j<6;j++) acc[i][j] *= sc;
        }
    }

    int L = pa.L[mi];
    if (L > 0) {
        float* O = pa.Out[mi];
#pragma unroll
        for (int i=0;i<4;i++) {
            int gr = tile*64 + m0 + i;
            int bb = gr / L, pp = gr - bb*L;
            float* base = O + (long)bb*H*L + pp;
#pragma unroll
            for (int j=0;j<6;j++) base[(n0+j)*L] = acc[i][j];
        }
    } else {
        float* O = pa.Out[mi] + (long)tile*64*H;
#pragma unroll
        for (int i=0;i<4;i++)
#pragma unroll
            for (int j=0;j<6;j++) O[(m0+i)*H + n0 + j] = acc[i][j];
    }
}

// ---------------- K2: out[i,j] = 0.5*( t[i].d[j] + t[i].v[j] ) ----------------
__global__ void gg_kernel(float* __restrict__ out)
{
    int i = blockIdx.x, j = threadIdx.x;
    const float* ti = g_t + i*H;
    const float* dj = g_d + j*H;
    const float* vj = g_v + j*H;
    float s = 0.f;
#pragma unroll 8
    for (int h=0;h<H;h++) s += ti[h]*(dj[h]+vj[h]);
    out[i*64+j] = 0.5f*s;
}

// ---------------- K3: TGL per pair (b,c) ----------------
// scores = Q[b](128x96) @ K[c]^T -> softmax rows -> w = mean_q attn ->
// ctx = w.V[c] -> LN -> l2n -> dot with d[b] ; out += 0.5*val
__global__ __launch_bounds__(256,2) void tgl_kernel(
    const float* __restrict__ lng, const float* __restrict__ lnb,
    float* __restrict__ out)
{
    extern __shared__ float sm[];
    float* Qs = sm;               // [96][128] h-major
    float* Ks = sm + H*QLEN;      // [96][128]
    float* Ss = sm;               // alias [128][128] after GEMM (Qs+Ks dead)
    float* invden = sm + 2*H*QLEN;    // [128]
    float* wv     = invden + 128;     // [128]
    float* ctxs   = wv + 128;         // [96]

    int tid = threadIdx.x;
    int b = blockIdx.y, c = blockIdx.x;
    int tm = tid >> 4, tn = tid & 15;   // 16 x 16
    int m0 = tm*8, n0 = tn*8;

    const float* Qg = g_Qt + (long)b*H*QLEN;
    const float* Kg = g_Kt + (long)c*H*QLEN;

    // linear coalesced copies, conflict-free
    for (int idx=tid; idx<H*QLEN/4; idx+=256) {
        ((float4*)Qs)[idx] = ((const float4*)Qg)[idx];
        ((float4*)Ks)[idx] = ((const float4*)Kg)[idx];
    }
    __syncthreads();

    float acc[8][8];
#pragma unroll
    for (int i=0;i<8;i++)
#pragma unroll
        for (int j=0;j<8;j++) acc[i][j]=0.f;

#pragma unroll 4
    for (int h=0;h<H;h++) {
        float4 a0 = *(const float4*)&Qs[h*QLEN + m0];
        float4 a1 = *(const float4*)&Qs[h*QLEN + m0 + 4];
        float4 b0 = *(const float4*)&Ks[h*QLEN + n0];
        float4 b1 = *(const float4*)&Ks[h*QLEN + n0 + 4];
        float a[8] = {a0.x,a0.y,a0.z,a0.w,a1.x,a1.y,a1.z,a1.w};
        float bb[8] = {b0.x,b0.y,b0.z,b0.w,b1.x,b1.y,b1.z,b1.w};
#pragma unroll
        for (int i=0;i<8;i++)
#pragma unroll
            for (int j=0;j<8;j++) acc[i][j] += a[i]*bb[j];
    }
    __syncthreads();   // Qs/Ks reads done; alias as Ss

    const float SC = 0.1020620726159658f;  // 1/sqrt(96)
#pragma unroll
    for (int i=0;i<8;i++) {
        float4 s0 = make_float4(acc[i][0]*SC, acc[i][1]*SC, acc[i][2]*SC, acc[i][3]*SC);
        float4 s1 = make_float4(acc[i][4]*SC, acc[i][5]*SC, acc[i][6]*SC, acc[i][7]*SC);
        *(float4*)&Ss[(m0+i)*128 + n0]     = s0;
        *(float4*)&Ss[(m0+i)*128 + n0 + 4] = s1;
    }
    __syncthreads();

    // row softmax: 8 warps x 16 rows
    {
        int w = tid>>5, lane = tid&31;
        for (int r=0;r<16;r++) {
            int row = w*16 + r;
            float* Sr = Ss + row*128;
            float v0=Sr[lane], v1=Sr[lane+32], v2=Sr[lane+64], v3=Sr[lane+96];
            float m = fmaxf(fmaxf(v0,v1), fmaxf(v2,v3));
#pragma unroll
            for (int o=16;o;o>>=1) m = fmaxf(m, __shfl_xor_sync(0xffffffffu,m,o));
            float e0=__expf(v0-m), e1=__expf(v1-m), e2=__expf(v2-m), e3=__expf(v3-m);
            float s = e0+e1+e2+e3;
#pragma unroll
            for (int o=16;o;o>>=1) s += __shfl_xor_sync(0xffffffffu,s,o);
            Sr[lane]=e0; Sr[lane+32]=e1; Sr[lane+64]=e2; Sr[lane+96]=e3;
            if (lane==0) invden[row] = 1.f/s;
        }
    }
    __syncthreads();

    // w[k] = (1/128) sum_q exp[q,k] * invden[q]
    if (tid < 128) {
        float s = 0.f;
#pragma unroll 4
        for (int q=0;q<128;q++) s += Ss[q*128 + tid] * invden[q];
        wv[tid] = s * (1.f/128.f);
    }
    __syncthreads();

    // context[h] = sum_k w[k]*V_t[h][k]  (V rows contiguous in global; read from L2)
    if (tid < 96) {
        const float* Vr = g_Vt + (long)c*H*QLEN + tid*QLEN;
        float s = 0.f;
#pragma unroll
        for (int k4=0;k4<QLEN/4;k4++) {
            float4 v = ((const float4*)Vr)[k4];
            s += wv[k4*4]*v.x + wv[k4*4+1]*v.y + wv[k4*4+2]*v.z + wv[k4*4+3]*v.w;
        }
        ctxs[tid] = s;
    }
    __syncthreads();

    // LayerNorm + l2n + dot(d[b]) on warp 0
    if (tid < 32) {
        float x0=ctxs[tid], x1=ctxs[tid+32], x2=ctxs[tid+64];
        float mu = x0+x1+x2;
#pragma unroll
        for (int o=16;o;o>>=1) mu += __shfl_xor_sync(0xffffffffu,mu,o);
        mu *= (1.f/96.f);
        float d0=x0-mu, d1=x1-mu, d2=x2-mu;
        float var = d0*d0 + d1*d1 + d2*d2;
#pragma unroll
        for (int o=16;o;o>>=1) var += __shfl_xor_sync(0xffffffffu,var,o);
        var *= (1.f/96.f);
        float rstd = rsqrtf(var + 1e-5f);
        float n0v = d0*rstd*lng[tid]    + lnb[tid];
        float n1v = d1*rstd*lng[tid+32] + lnb[tid+32];
        float n2v = d2*rstd*lng[tid+64] + lnb[tid+64];
        float ss = n0v*n0v + n1v*n1v + n2v*n2v;
#pragma unroll
        for (int o=16;o;o>>=1) ss += __shfl_xor_sync(0xffffffffu,ss,o);
        float sc = 1.f / fmaxf(sqrtf(ss), 1e-6f);
        const float* db = g_d + b*H;
        float dt = db[tid]*n0v + db[tid+32]*n1v + db[tid+64]*n2v;
#pragma unroll
        for (int o=16;o;o>>=1) dt += __shfl_xor_sync(0xffffffffu,dt,o);
        if (tid==0) out[b*64+c] += 0.5f * (dt*sc);
    }
}

// ---------------- K4: CLL per pair (b,c): max over t_tok[b] @ v_pat[c]^T ----------------
// 448 threads = 16(tm) x 28(tn), micro 8x8 over 128 x 224 (padded), masked max
__global__ __launch_bounds__(448,1) void cll_kernel(float* __restrict__ out)
{
    extern __shared__ float sm[];
    float* As  = sm;                 // [96][128] h-major
    float* Bs  = sm + H*QLEN;        // [96][224] h-major, zero-padded cols 196..223
    float* red = Bs + H*PPAD;        // [14]

    int tid = threadIdx.x;
    int b = blockIdx.y, c = blockIdx.x;
    int tm = tid/28, tn = tid%28;
    int m0 = tm*8,  n0 = tn*8;

    const float* Ag = g_ttt + (long)b*H*QLEN;
    const float* Bg = g_vpt + (long)c*H*PLEN;

    // load A (linear) and B (rows of 49 float4 + 7 float4 zero pad)
    for (int idx=tid; idx<H*QLEN/4; idx+=448)
        ((float4*)As)[idx] = ((const float4*)Ag)[idx];
    for (int idx=tid; idx<H*(PPAD/4); idx+=448) {
        int h = idx/(PPAD/4), s4 = idx%(PPAD/4);
        float4 v = (s4 < PLEN/4) ? ((const float4*)(Bg + h*PLEN))[s4]
                                 : make_float4(0.f,0.f,0.f,0.f);
        ((float4*)(Bs + h*PPAD))[s4] = v;
    }
    __syncthreads();

    float acc[8][8];
#pragma unroll
    for (int i=0;i<8;i++)
#pragma unroll
        for (int j=0;j<8;j++) acc[i][j]=0.f;

#pragma unroll 4
    for (int h=0;h<H;h++) {
        float4 a0 = *(const float4*)&As[h*QLEN + m0];
        float4 a1 = *(const float4*)&As[h*QLEN + m0 + 4];
        float4 b0 = *(const float4*)&Bs[h*PPAD + n0];
        float4 b1 = *(const float4*)&Bs[h*PPAD + n0 + 4];
        float a[8] = {a0.x,a0.y,a0.z,a0.w,a1.x,a1.y,a1.z,a1.w};
        float bb[8] = {b0.x,b0.y,b0.z,b0.w,b1.x,b1.y,b1.z,b1.w};
#pragma unroll
        for (int i=0;i<8;i++)
#pragma unroll
            for (int j=0;j<8;j++) acc[i][j] += a[i]*bb[j];
    }

    float m = -1e30f;
#pragma unroll
    for (int j=0;j<8;j++) {
        if (n0 + j < PLEN) {
#pragma unroll
            for (int i=0;i<8;i++) m = fmaxf(m, acc[i][j]);
        }
    }
#pragma unroll
    for (int o=16;o;o>>=1) m = fmaxf(m, __shfl_xor_sync(0xffffffffu,m,o));
    if ((tid&31)==0) red[tid>>5] = m;
    __syncthreads();
    if (tid==0) {
        float mm = red[0];
#pragma unroll
        for (int w=1;w<14;w++) mm = fmaxf(mm, red[w]);
        out[b*64+c] += 0.5f*mm;
    }
}

// ---------------- host ----------------
extern "C" void kernel_launch(void* const* d_in, const int* in_sizes, int n_in,
                              void* d_out, int out_size)
{
    const float* z_d_cls = (const float*)d_in[0];
    const float* Z_d_tok = (const float*)d_in[1];
    const float* z_t_cls = (const float*)d_in[2];
    const float* Z_t_tok = (const float*)d_in[3];
    const float* z_v_cls = (const float*)d_in[4];
    const float* Z_v_pat = (const float*)d_in[5];
    const float *W_t_cls=(const float*)d_in[6],  *b_t_cls=(const float*)d_in[7];
    const float *W_d_cls=(const float*)d_in[8],  *b_d_cls=(const float*)d_in[9];
    const float *W_v_cls=(const float*)d_in[10], *b_v_cls=(const float*)d_in[11];
    const float *W_t_tok=(const float*)d_in[12], *b_t_tok=(const float*)d_in[13];
    const float *W_v_pat=(const float*)d_in[14], *b_v_pat=(const float*)d_in[15];
    const float *W_q=(const float*)d_in[16], *b_q=(const float*)d_in[17];
    const float *W_k=(const float*)d_in[18], *b_k=(const float*)d_in[19];
    const float *W_v=(const float*)d_in[20], *b_v=(const float*)d_in[21];
    const float *ln_g=(const float*)d_in[22], *ln_b=(const float*)d_in[23];
    float* out = (float*)d_out;

    float *Qp,*Kp,*Vp,*ttp,*vpp,*tp,*dp,*vp;
    cudaGetSymbolAddress((void**)&Qp,  g_Qt);
    cudaGetSymbolAddress((void**)&Kp,  g_Kt);
    cudaGetSymbolAddress((void**)&Vp,  g_Vt);
    cudaGetSymbolAddress((void**)&ttp, g_ttt);
    cudaGetSymbolAddress((void**)&vpp, g_vpt);
    cudaGetSymbolAddress((void**)&tp,  g_t);
    cudaGetSymbolAddress((void**)&dp,  g_d);
    cudaGetSymbolAddress((void**)&vp,  g_v);

    const int SM3 = (2*H*QLEN + 128 + 128 + 96) * (int)sizeof(float);   // ~99.7 KB
    const int SM4 = (H*QLEN + H*PPAD + 16) * (int)sizeof(float);        // ~135.3 KB
    cudaFuncSetAttribute(tgl_kernel, cudaFuncAttributeMaxDynamicSharedMemorySize, SM3);
    cudaFuncSetAttribute(cll_kernel, cudaFuncAttributeMaxDynamicSharedMemorySize, SM4);

    // ---- one batched projection launch (all 8 matrices, fused l2n + transpose) ----
    ProjArgs pa;
    pa.X[0]=Z_d_tok; pa.W[0]=W_q;     pa.Bv[0]=b_q;     pa.Out[0]=Qp;  pa.l2n[0]=0; pa.L[0]=QLEN;
    pa.X[1]=Z_t_tok; pa.W[1]=W_k;     pa.Bv[1]=b_k;     pa.Out[1]=Kp;  pa.l2n[1]=0; pa.L[1]=QLEN;
    pa.X[2]=Z_t_tok; pa.W[2]=W_v;     pa.Bv[2]=b_v;     pa.Out[2]=Vp;  pa.l2n[2]=0; pa.L[2]=QLEN;
    pa.X[3]=Z_t_tok; pa.W[3]=W_t_tok; pa.Bv[3]=b_t_tok; pa.Out[3]=ttp; pa.l2n[3]=1; pa.L[3]=QLEN;
    pa.X[4]=Z_v_pat; pa.W[4]=W_v_pat; pa.Bv[4]=b_v_pat; pa.Out[4]=vpp; pa.l2n[4]=1; pa.L[4]=PLEN;
    pa.X[5]=z_t_cls; pa.W[5]=W_t_cls; pa.Bv[5]=b_t_cls; pa.Out[5]=tp;  pa.l2n[5]=1; pa.L[5]=0;
    pa.X[6]=z_d_cls; pa.W[6]=W_d_cls; pa.Bv[6]=b_d_cls; pa.Out[6]=dp;  pa.l2n[6]=1; pa.L[6]=0;
    pa.X[7]=z_v_cls; pa.W[7]=W_v_cls; pa.Bv[7]=b_v_cls; pa.Out[7]=vp;  pa.l2n[7]=1; pa.L[7]=0;
    int nt[8] = {128,128,128,128,196,1,1,1};
    pa.tile_start[0]=0;
    for (int i=0;i<8;i++) pa.tile_start[i+1]=pa.tile_start[i]+nt[i];

    proj_all<<<pa.tile_start[8],256>>>(pa);

    // out = 0.5*(S_TGG + S_CGG)
    gg_kernel<<<64,64>>>(out);
    // out += 0.5*S_TGL
    tgl_kernel<<<dim3(64,64),256,SM3>>>(ln_g, ln_b, out);
    // out += 0.5*S_CLL
    cll_kernel<<<dim3(64,64),448,SM4>>>(out);
}

// round 6
// speedup vs baseline: 1.9193x; 1.3914x over previous
#include <cuda_runtime.h>
#include <cuda_bf16.h>
#include <cstdint>

#define EIN 512
#define H   96
#define BSZ 64
#define QLEN 128
#define PLEN 196

// ---------------- scratch (device globals; zero-initialized) ----------------
__device__ float g_Qt [BSZ*H*QLEN];   // [b][h][q] h-major fp32
__device__ float g_Kt [BSZ*H*QLEN];
__device__ float g_Vt [BSZ*H*QLEN];
__device__ float g_t [BSZ*H];
__device__ float g_d [BSZ*H];
__device__ float g_v [BSZ*H];

// bf16 hi/lo split operands for CLL mma.sync path (plain row-major)
__device__ __nv_bfloat16 g_Ahi[BSZ*QLEN*H];   // [b][t][h]
__device__ __nv_bfloat16 g_Alo[BSZ*QLEN*H];
__device__ __nv_bfloat16 g_Bhi[BSZ*PLEN*H];   // [c][p][h]
__device__ __nv_bfloat16 g_Blo[BSZ*PLEN*H];

// ---------------- PTX helpers (plain-target-safe: ldmatrix + mma.sync) ----------------
__device__ __forceinline__ uint32_t smem_u32(const void* p) {
    uint32_t a;
    asm("{ .reg .u64 t; cvta.to.shared.u64 t, %1; cvt.u32.u64 %0, t; }"
        : "=r"(a) : "l"(p));
    return a;
}
__device__ __forceinline__ void ldsm_x4(uint32_t* r, uint32_t addr) {
    asm volatile("ldmatrix.sync.aligned.m8n8.x4.shared.b16 {%0,%1,%2,%3}, [%4];"
        : "=r"(r[0]),"=r"(r[1]),"=r"(r[2]),"=r"(r[3]) : "r"(addr));
}
__device__ __forceinline__ void ldsm_x2(uint32_t* r, uint32_t addr) {
    asm volatile("ldmatrix.sync.aligned.m8n8.x2.shared.b16 {%0,%1}, [%2];"
        : "=r"(r[0]),"=r"(r[1]) : "r"(addr));
}
__device__ __forceinline__ void mma16816(float* d, const uint32_t* a, const uint32_t* b) {
    asm volatile("mma.sync.aligned.m16n8k16.row.col.f32.bf16.bf16.f32 "
        "{%0,%1,%2,%3}, {%4,%5,%6,%7}, {%8,%9}, {%0,%1,%2,%3};"
        : "+f"(d[0]),"+f"(d[1]),"+f"(d[2]),"+f"(d[3])
        : "r"(a[0]),"r"(a[1]),"r"(a[2]),"r"(a[3]), "r"(b[0]),"r"(b[1]));
}

// ---------------- K1: batched projection (all 8), fused l2n / transpose / bf16-split ----------------
struct ProjArgs {
    const float* X[8];
    const float* W[8];
    const float* Bv[8];
    float*       Out[8];
    void*        Out2[8];
    int          tile_start[9];
    int          l2n[8];
    int          L[8];       // >0: fp32 transposed [row/L][96][L]
    int          mode[8];    // 0: fp32, 1: bf16 A (128 rows/b), 2: bf16 B (196 rows/c)
};

__global__ __launch_bounds__(256) void proj_all(ProjArgs pa)
{
    __shared__ float Xs[64*33];
    __shared__ float Ws[96*33];

    int bid = blockIdx.x;
    int mi = 0;
#pragma unroll
    for (int i=1;i<8;i++) if (bid >= pa.tile_start[i]) mi = i;
    int tile = bid - pa.tile_start[mi];

    const float* Xb   = pa.X[mi] + (long)tile*64*EIN;
    const float* W    = pa.W[mi];
    const float* bias = pa.Bv[mi];

    int tid = threadIdx.x;
    int tm = tid >> 4, tn = tid & 15;
    int m0 = tm*4,  n0 = tn*6;

    float acc[4][6];
#pragma unroll
    for (int i=0;i<4;i++)
#pragma unroll
        for (int j=0;j<6;j++) acc[i][j]=0.f;

    for (int k0=0;k0<EIN;k0+=32) {
        __syncthreads();
        for (int idx=tid; idx<64*32; idx+=256) {
            int m = idx>>5, kk = idx&31;
            Xs[m*33+kk] = Xb[m*EIN + k0 + kk];
        }
        for (int idx=tid; idx<96*32; idx+=256) {
            int n = idx>>5, kk = idx&31;
            Ws[n*33+kk] = W[n*EIN + k0 + kk];
        }
        __syncthreads();
#pragma unroll 8
        for (int kk=0;kk<32;kk++) {
            float a[4], b[6];
#pragma unroll
            for (int i=0;i<4;i++) a[i]=Xs[(m0+i)*33+kk];
#pragma unroll
            for (int j=0;j<6;j++) b[j]=Ws[(n0+j)*33+kk];
#pragma unroll
            for (int i=0;i<4;i++)
#pragma unroll
                for (int j=0;j<6;j++) acc[i][j] += a[i]*b[j];
        }
    }

#pragma unroll
    for (int i=0;i<4;i++)
#pragma unroll
        for (int j=0;j<6;j++) acc[i][j] += bias[n0+j];

    if (pa.l2n[mi]) {
        __syncthreads();
#pragma unroll
        for (int i=0;i<4;i++) {
            float ss = 0.f;
#pragma unroll
            for (int j=0;j<6;j++) ss += acc[i][j]*acc[i][j];
            Xs[(m0+i)*17 + tn] = ss;
        }
        __syncthreads();
        if (tid < 64) {
            float s = 0.f;
#pragma unroll
            for (int t=0;t<16;t++) s += Xs[tid*17+t];
            Ws[tid] = 1.f / fmaxf(sqrtf(s), 1e-6f);
        }
        __syncthreads();
#pragma unroll
        for (int i=0;i<4;i++) {
            float sc = Ws[m0+i];
#pragma unroll
            for (int j=0;j<6;j++) acc[i][j] *= sc;
        }
    }

    int mode = pa.mode[mi];
    if (mode) {
        int perlen = (mode==1) ? 128 : 196;
        __nv_bfloat16* hiB = (__nv_bfloat16*)pa.Out[mi];
        __nv_bfloat16* loB = (__nv_bfloat16*)pa.Out2[mi];
#pragma unroll
        for (int i=0;i<4;i++) {
            int gr = tile*64 + m0 + i;
            int bb = gr / perlen, rr = gr - bb*perlen;
            long base = ((long)bb*perlen + rr)*H + n0;
#pragma unroll
            for (int j=0;j<6;j++) {
                float x = acc[i][j];
                __nv_bfloat16 hv = __float2bfloat16(x);
                __nv_bfloat16 lv = __float2bfloat16(x - __bfloat162float(hv));
                hiB[base+j] = hv;
                loB[base+j] = lv;
            }
        }
    } else {
        int L = pa.L[mi];
        if (L > 0) {
            float* O = pa.Out[mi];
#pragma unroll
            for (int i=0;i<4;i++) {
                int gr = tile*64 + m0 + i;
                int bb = gr / L, pp = gr - bb*L;
                float* base = O + (long)bb*H*L + pp;
#pragma unroll
                for (int j=0;j<6;j++) base[(n0+j)*L] = acc[i][j];
            }
        } else {
            float* O = pa.Out[mi] + (long)tile*64*H;
#pragma unroll
            for (int i=0;i<4;i++)
#pragma unroll
                for (int j=0;j<6;j++) O[(m0+i)*H + n0 + j] = acc[i][j];
        }
    }
}

// ---------------- K2: out[i,j] = 0.5*( t[i].d[j] + t[i].v[j] ) ----------------
__global__ void gg_kernel(float* __restrict__ out)
{
    int i = blockIdx.x, j = threadIdx.x;
    const float* ti = g_t + i*H;
    const float* dj = g_d + j*H;
    const float* vj = g_v + j*H;
    float s = 0.f;
#pragma unroll 8
    for (int h=0;h<H;h++) s += ti[h]*(dj[h]+vj[h]);
    out[i*64+j] = 0.5f*s;
}

// ---------------- K3: TGL per pair (b,c) (SIMT fp32) ----------------
__global__ __launch_bounds__(256,2) void tgl_kernel(
    const float* __restrict__ lng, const float* __restrict__ lnb,
    float* __restrict__ out)
{
    extern __shared__ float sm[];
    float* Qs = sm;               // [96][128]
    float* Ks = sm + H*QLEN;
    float* Ss = sm;               // alias [128][128]
    float* invden = sm + 2*H*QLEN;
    float* wv     = invden + 128;
    float* ctxs   = wv + 128;

    int tid = threadIdx.x;
    int b = blockIdx.y, c = blockIdx.x;
    int tm = tid >> 4, tn = tid & 15;
    int m0 = tm*8, n0 = tn*8;

    const float* Qg = g_Qt + (long)b*H*QLEN;
    const float* Kg = g_Kt + (long)c*H*QLEN;

    for (int idx=tid; idx<H*QLEN/4; idx+=256) {
        ((float4*)Qs)[idx] = ((const float4*)Qg)[idx];
        ((float4*)Ks)[idx] = ((const float4*)Kg)[idx];
    }
    __syncthreads();

    float acc[8][8];
#pragma unroll
    for (int i=0;i<8;i++)
#pragma unroll
        for (int j=0;j<8;j++) acc[i][j]=0.f;

#pragma unroll 4
    for (int h=0;h<H;h++) {
        float4 a0 = *(const float4*)&Qs[h*QLEN + m0];
        float4 a1 = *(const float4*)&Qs[h*QLEN + m0 + 4];
        float4 b0 = *(const float4*)&Ks[h*QLEN + n0];
        float4 b1 = *(const float4*)&Ks[h*QLEN + n0 + 4];
        float a[8] = {a0.x,a0.y,a0.z,a0.w,a1.x,a1.y,a1.z,a1.w};
        float bb[8] = {b0.x,b0.y,b0.z,b0.w,b1.x,b1.y,b1.z,b1.w};
#pragma unroll
        for (int i=0;i<8;i++)
#pragma unroll
            for (int j=0;j<8;j++) acc[i][j] += a[i]*bb[j];
    }
    __syncthreads();

    const float SC = 0.1020620726159658f;
#pragma unroll
    for (int i=0;i<8;i++) {
        float4 s0 = make_float4(acc[i][0]*SC, acc[i][1]*SC, acc[i][2]*SC, acc[i][3]*SC);
        float4 s1 = make_float4(acc[i][4]*SC, acc[i][5]*SC, acc[i][6]*SC, acc[i][7]*SC);
        *(float4*)&Ss[(m0+i)*128 + n0]     = s0;
        *(float4*)&Ss[(m0+i)*128 + n0 + 4] = s1;
    }
    __syncthreads();

    {
        int w = tid>>5, lane = tid&31;
        for (int r=0;r<16;r++) {
            int row = w*16 + r;
            float* Sr = Ss + row*128;
            float v0=Sr[lane], v1=Sr[lane+32], v2=Sr[lane+64], v3=Sr[lane+96];
            float m = fmaxf(fmaxf(v0,v1), fmaxf(v2,v3));
#pragma unroll
            for (int o=16;o;o>>=1) m = fmaxf(m, __shfl_xor_sync(0xffffffffu,m,o));
            float e0=__expf(v0-m), e1=__expf(v1-m), e2=__expf(v2-m), e3=__expf(v3-m);
            float s = e0+e1+e2+e3;
#pragma unroll
            for (int o=16;o;o>>=1) s += __shfl_xor_sync(0xffffffffu,s,o);
            Sr[lane]=e0; Sr[lane+32]=e1; Sr[lane+64]=e2; Sr[lane+96]=e3;
            if (lane==0) invden[row] = 1.f/s;
        }
    }
    __syncthreads();

    if (tid < 128) {
        float s = 0.f;
#pragma unroll 4
        for (int q=0;q<128;q++) s += Ss[q*128 + tid] * invden[q];
        wv[tid] = s * (1.f/128.f);
    }
    __syncthreads();

    if (tid < 96) {
        const float* Vr = g_Vt + (long)c*H*QLEN + tid*QLEN;
        float s = 0.f;
#pragma unroll
        for (int k4=0;k4<QLEN/4;k4++) {
            float4 v = ((const float4*)Vr)[k4];
            s += wv[k4*4]*v.x + wv[k4*4+1]*v.y + wv[k4*4+2]*v.z + wv[k4*4+3]*v.w;
        }
        ctxs[tid] = s;
    }
    __syncthreads();

    if (tid < 32) {
        float x0=ctxs[tid], x1=ctxs[tid+32], x2=ctxs[tid+64];
        float mu = x0+x1+x2;
#pragma unroll
        for (int o=16;o;o>>=1) mu += __shfl_xor_sync(0xffffffffu,mu,o);
        mu *= (1.f/96.f);
        float d0=x0-mu, d1=x1-mu, d2=x2-mu;
        float var = d0*d0 + d1*d1 + d2*d2;
#pragma unroll
        for (int o=16;o;o>>=1) var += __shfl_xor_sync(0xffffffffu,var,o);
        var *= (1.f/96.f);
        float rstd = rsqrtf(var + 1e-5f);
        float n0v = d0*rstd*lng[tid]    + lnb[tid];
        float n1v = d1*rstd*lng[tid+32] + lnb[tid+32];
        float n2v = d2*rstd*lng[tid+64] + lnb[tid+64];
        float ss = n0v*n0v + n1v*n1v + n2v*n2v;
#pragma unroll
        for (int o=16;o;o>>=1) ss += __shfl_xor_sync(0xffffffffu,ss,o);
        float sc = 1.f / fmaxf(sqrtf(ss), 1e-6f);
        const float* db = g_d + b*H;
        float dt = db[tid]*n0v + db[tid+32]*n1v + db[tid+64]*n2v;
#pragma unroll
        for (int o=16;o;o>>=1) dt += __shfl_xor_sync(0xffffffffu,dt,o);
        if (tid==0) out[b*64+c] += 0.5f * (dt*sc);
    }
}

// ---------------- K4: CLL via mma.sync bf16 split-precision ----------------
// Per (b,c): masked max over D[128x200] = A(128x96) @ B(200x96)^T,
// D = Ahi*Bhi + Ahi*Blo + Alo*Bhi, fp32 accum. 8 warps x 16-row bands.
#define RPAD 104                      // padded row length (bf16) -> 208B, LDSM conflict-free
#define OFF_AHI 0
#define OFF_ALO (OFF_AHI + 128*RPAD*2)
#define OFF_BHI (OFF_ALO + 128*RPAD*2)
#define OFF_BLO (OFF_BHI + 200*RPAD*2)
#define OFF_RED (OFF_BLO + 200*RPAD*2)
#define SM_CLL  (OFF_RED + 64)

__global__ __launch_bounds__(256,1) void cll_mma(float* __restrict__ out)
{
    extern __shared__ char smem[];
    uint32_t sb = smem_u32(smem);
    int tid = threadIdx.x;
    int wid = tid >> 5, lane = tid & 31;
    int b = blockIdx.y, c = blockIdx.x;

    // ---- load tiles (96 bf16 = 12 uint4 per row; smem row stride 13 uint4) ----
    {
        const uint4* Ah = (const uint4*)(g_Ahi + (long)b*QLEN*H);
        const uint4* Al = (const uint4*)(g_Alo + (long)b*QLEN*H);
        uint4* dAh = (uint4*)(smem + OFF_AHI);
        uint4* dAl = (uint4*)(smem + OFF_ALO);
        for (int idx=tid; idx<128*12; idx+=256) {
            int r = idx/12, q = idx%12;
            dAh[r*13+q] = Ah[idx];
            dAl[r*13+q] = Al[idx];
        }
        const uint4* Bh = (const uint4*)(g_Bhi + (long)c*PLEN*H);
        const uint4* Bl = (const uint4*)(g_Blo + (long)c*PLEN*H);
        uint4* dBh = (uint4*)(smem + OFF_BHI);
        uint4* dBl = (uint4*)(smem + OFF_BLO);
        for (int idx=tid; idx<196*12; idx+=256) {
            int r = idx/12, q = idx%12;
            dBh[r*13+q] = Bh[idx];
            dBl[r*13+q] = Bl[idx];
        }
        // zero pad rows 196..199 (only k-bytes 0..191 are ever read, zero all 13)
        uint4 z = make_uint4(0,0,0,0);
        for (int idx=tid; idx<4*13; idx+=256) {
            int r = 196 + idx/13, q = idx%13;
            dBh[r*13+q] = z;
            dBl[r*13+q] = z;
        }
    }
    __syncthreads();

    // ---- A fragments for this warp's 16-row band: 6 k-steps, hi+lo ----
    int m0 = wid*16;
    uint32_t ahi[6][4], alo[6][4];
    {
        // ldmatrix.x4 lane mapping: row = m0 + (lane&7) + ((lane>>3)&1)*8, chunk=((lane>>4)&1)*16B
        int rrow = m0 + (lane & 7) + ((lane >> 3) & 1) * 8;
        int rchk = ((lane >> 4) & 1) * 16;
#pragma unroll
        for (int ks=0; ks<6; ks++) {
            uint32_t addr = sb + OFF_AHI + rrow*(RPAD*2) + ks*32 + rchk;
            ldsm_x4(ahi[ks], addr);
            addr = sb + OFF_ALO + rrow*(RPAD*2) + ks*32 + rchk;
            ldsm_x4(alo[ks], addr);
        }
    }

    // ---- loop over 25 n-tiles; accumulate 3 products; masked max ----
    float mbest = -1e30f;
    int brow = lane & 7;
    int bchk = ((lane >> 3) & 1) * 16;
    for (int nt=0; nt<25; nt++) {
        float acc[4] = {0.f, 0.f, 0.f, 0.f};
        int n0 = nt*8;
        uint32_t baddr_h = sb + OFF_BHI + (n0+brow)*(RPAD*2) + bchk;
        uint32_t baddr_l = sb + OFF_BLO + (n0+brow)*(RPAD*2) + bchk;
#pragma unroll
        for (int ks=0; ks<6; ks++) {
            uint32_t bh[2], bl[2];
            ldsm_x2(bh, baddr_h + ks*32);
            ldsm_x2(bl, baddr_l + ks*32);
            mma16816(acc, ahi[ks], bh);
            mma16816(acc, alo[ks], bh);
            mma16816(acc, ahi[ks], bl);
        }
        int col0 = n0 + (lane & 3)*2;
        if (col0 < PLEN)   mbest = fmaxf(mbest, fmaxf(acc[0], acc[2]));
        if (col0+1 < PLEN) mbest = fmaxf(mbest, fmaxf(acc[1], acc[3]));
    }

#pragma unroll
    for (int o=16;o;o>>=1) mbest = fmaxf(mbest, __shfl_xor_sync(0xffffffffu,mbest,o));
    float* red = (float*)(smem + OFF_RED);
    if (lane == 0) red[wid] = mbest;
    __syncthreads();
    if (tid == 0) {
        float m = red[0];
#pragma unroll
        for (int w=1;w<8;w++) m = fmaxf(m, red[w]);
        out[b*64+c] += 0.5f*m;
    }
}

// ---------------- host ----------------
extern "C" void kernel_launch(void* const* d_in, const int* in_sizes, int n_in,
                              void* d_out, int out_size)
{
    const float* z_d_cls = (const float*)d_in[0];
    const float* Z_d_tok = (const float*)d_in[1];
    const float* z_t_cls = (const float*)d_in[2];
    const float* Z_t_tok = (const float*)d_in[3];
    const float* z_v_cls = (const float*)d_in[4];
    const float* Z_v_pat = (const float*)d_in[5];
    const float *W_t_cls=(const float*)d_in[6],  *b_t_cls=(const float*)d_in[7];
    const float *W_d_cls=(const float*)d_in[8],  *b_d_cls=(const float*)d_in[9];
    const float *W_v_cls=(const float*)d_in[10], *b_v_cls=(const float*)d_in[11];
    const float *W_t_tok=(const float*)d_in[12], *b_t_tok=(const float*)d_in[13];
    const float *W_v_pat=(const float*)d_in[14], *b_v_pat=(const float*)d_in[15];
    const float *W_q=(const float*)d_in[16], *b_q=(const float*)d_in[17];
    const float *W_k=(const float*)d_in[18], *b_k=(const float*)d_in[19];
    const float *W_v=(const float*)d_in[20], *b_v=(const float*)d_in[21];
    const float *ln_g=(const float*)d_in[22], *ln_b=(const float*)d_in[23];
    float* out = (float*)d_out;

    float *Qp,*Kp,*Vp,*tp,*dp,*vp;
    void *ahi,*alo,*bhi,*blo;
    cudaGetSymbolAddress((void**)&Qp,  g_Qt);
    cudaGetSymbolAddress((void**)&Kp,  g_Kt);
    cudaGetSymbolAddress((void**)&Vp,  g_Vt);
    cudaGetSymbolAddress((void**)&tp,  g_t);
    cudaGetSymbolAddress((void**)&dp,  g_d);
    cudaGetSymbolAddress((void**)&vp,  g_v);
    cudaGetSymbolAddress(&ahi, g_Ahi);
    cudaGetSymbolAddress(&alo, g_Alo);
    cudaGetSymbolAddress(&bhi, g_Bhi);
    cudaGetSymbolAddress(&blo, g_Blo);

    const int SM3 = (2*H*QLEN + 128 + 128 + 96) * (int)sizeof(float);
    cudaFuncSetAttribute(tgl_kernel, cudaFuncAttributeMaxDynamicSharedMemorySize, SM3);
    cudaFuncSetAttribute(cll_mma,    cudaFuncAttributeMaxDynamicSharedMemorySize, SM_CLL);

    ProjArgs pa;
    for (int i=0;i<8;i++) { pa.Out2[i]=nullptr; pa.mode[i]=0; pa.L[i]=0; pa.l2n[i]=0; }
    pa.X[0]=Z_d_tok; pa.W[0]=W_q;     pa.Bv[0]=b_q;     pa.Out[0]=Qp;  pa.L[0]=QLEN;
    pa.X[1]=Z_t_tok; pa.W[1]=W_k;     pa.Bv[1]=b_k;     pa.Out[1]=Kp;  pa.L[1]=QLEN;
    pa.X[2]=Z_t_tok; pa.W[2]=W_v;     pa.Bv[2]=b_v;     pa.Out[2]=Vp;  pa.L[2]=QLEN;
    pa.X[3]=Z_t_tok; pa.W[3]=W_t_tok; pa.Bv[3]=b_t_tok; pa.Out[3]=(float*)ahi; pa.Out2[3]=alo; pa.l2n[3]=1; pa.mode[3]=1;
    pa.X[4]=Z_v_pat; pa.W[4]=W_v_pat; pa.Bv[4]=b_v_pat; pa.Out[4]=(float*)bhi; pa.Out2[4]=blo; pa.l2n[4]=1; pa.mode[4]=2;
    pa.X[5]=z_t_cls; pa.W[5]=W_t_cls; pa.Bv[5]=b_t_cls; pa.Out[5]=tp;  pa.l2n[5]=1;
    pa.X[6]=z_d_cls; pa.W[6]=W_d_cls; pa.Bv[6]=b_d_cls; pa.Out[6]=dp;  pa.l2n[6]=1;
    pa.X[7]=z_v_cls; pa.W[7]=W_v_cls; pa.Bv[7]=b_v_cls; pa.Out[7]=vp;  pa.l2n[7]=1;
    int nt[8] = {128,128,128,128,196,1,1,1};
    pa.tile_start[0]=0;
    for (int i=0;i<8;i++) pa.tile_start[i+1]=pa.tile_start[i]+nt[i];

    proj_all<<<pa.tile_start[8],256>>>(pa);

    // out = 0.5*(S_TGG + S_CGG)
    gg_kernel<<<64,64>>>(out);
    // out += 0.5*S_TGL
    tgl_kernel<<<dim3(64,64),256,SM3>>>(ln_g, ln_b, out);
    // out += 0.5*S_CLL  (mma.sync bf16 split)
    cll_mma<<<dim3(64,64),256,SM_CLL>>>(out);
}

// round 7
// speedup vs baseline: 2.3914x; 1.2460x over previous
#include <cuda_runtime.h>
#include <cuda_bf16.h>
#include <cstdint>

#define EIN 512
#define H   96
#define BSZ 64
#define QLEN 128
#define PLEN 196

// ---------------- scratch (device globals; zero-initialized) ----------------
__device__ float g_Vt [BSZ*H*QLEN];   // [c][h][q] h-major fp32
__device__ float g_t [BSZ*H];
__device__ float g_d [BSZ*H];
__device__ float g_v [BSZ*H];

// bf16 hi/lo split operands (plain row-major [b][row][h])
__device__ __nv_bfloat16 g_Qhi[BSZ*QLEN*H];
__device__ __nv_bfloat16 g_Qlo[BSZ*QLEN*H];
__device__ __nv_bfloat16 g_Khi[BSZ*QLEN*H];
__device__ __nv_bfloat16 g_Klo[BSZ*QLEN*H];
__device__ __nv_bfloat16 g_Ahi[BSZ*QLEN*H];   // t_tok
__device__ __nv_bfloat16 g_Alo[BSZ*QLEN*H];
__device__ __nv_bfloat16 g_Bhi[BSZ*PLEN*H];   // v_patch
__device__ __nv_bfloat16 g_Blo[BSZ*PLEN*H];

// ---------------- PTX helpers (plain-target-safe: ldmatrix + mma.sync) ----------------
__device__ __forceinline__ uint32_t smem_u32(const void* p) {
    uint32_t a;
    asm("{ .reg .u64 t; cvta.to.shared.u64 t, %1; cvt.u32.u64 %0, t; }"
        : "=r"(a) : "l"(p));
    return a;
}
__device__ __forceinline__ void ldsm_x4(uint32_t* r, uint32_t addr) {
    asm volatile("ldmatrix.sync.aligned.m8n8.x4.shared.b16 {%0,%1,%2,%3}, [%4];"
        : "=r"(r[0]),"=r"(r[1]),"=r"(r[2]),"=r"(r[3]) : "r"(addr));
}
__device__ __forceinline__ void ldsm_x2(uint32_t* r, uint32_t addr) {
    asm volatile("ldmatrix.sync.aligned.m8n8.x2.shared.b16 {%0,%1}, [%2];"
        : "=r"(r[0]),"=r"(r[1]) : "r"(addr));
}
__device__ __forceinline__ void mma16816(float* d, const uint32_t* a, const uint32_t* b) {
    asm volatile("mma.sync.aligned.m16n8k16.row.col.f32.bf16.bf16.f32 "
        "{%0,%1,%2,%3}, {%4,%5,%6,%7}, {%8,%9}, {%0,%1,%2,%3};"
        : "+f"(d[0]),"+f"(d[1]),"+f"(d[2]),"+f"(d[3])
        : "r"(a[0]),"r"(a[1]),"r"(a[2]),"r"(a[3]), "r"(b[0]),"r"(b[1]));
}

// ---------------- K1: batched projection (all 8), fused l2n / transpose / bf16-split ----------------
struct ProjArgs {
    const float* X[8];
    const float* W[8];
    const float* Bv[8];
    float*       Out[8];
    void*        Out2[8];
    int          tile_start[9];
    int          l2n[8];
    int          L[8];       // >0: fp32 transposed [row/L][96][L]
    int          mode[8];    // 0: fp32, 1: bf16 split 128 rows/b, 2: bf16 split 196 rows/c
};

__global__ __launch_bounds__(256) void proj_all(ProjArgs pa)
{
    __shared__ float Xs[64*33];
    __shared__ float Ws[96*33];

    int bid = blockIdx.x;
    int mi = 0;
#pragma unroll
    for (int i=1;i<8;i++) if (bid >= pa.tile_start[i]) mi = i;
    int tile = bid - pa.tile_start[mi];

    const float* Xb   = pa.X[mi] + (long)tile*64*EIN;
    const float* W    = pa.W[mi];
    const float* bias = pa.Bv[mi];

    int tid = threadIdx.x;
    int tm = tid >> 4, tn = tid & 15;
    int m0 = tm*4,  n0 = tn*6;

    float acc[4][6];
#pragma unroll
    for (int i=0;i<4;i++)
#pragma unroll
        for (int j=0;j<6;j++) acc[i][j]=0.f;

    for (int k0=0;k0<EIN;k0+=32) {
        __syncthreads();
        for (int idx=tid; idx<64*32; idx+=256) {
            int m = idx>>5, kk = idx&31;
            Xs[m*33+kk] = Xb[m*EIN + k0 + kk];
        }
        for (int idx=tid; idx<96*32; idx+=256) {
            int n = idx>>5, kk = idx&31;
            Ws[n*33+kk] = W[n*EIN + k0 + kk];
        }
        __syncthreads();
#pragma unroll 8
        for (int kk=0;kk<32;kk++) {
            float a[4], b[6];
#pragma unroll
            for (int i=0;i<4;i++) a[i]=Xs[(m0+i)*33+kk];
#pragma unroll
            for (int j=0;j<6;j++) b[j]=Ws[(n0+j)*33+kk];
#pragma unroll
            for (int i=0;i<4;i++)
#pragma unroll
                for (int j=0;j<6;j++) acc[i][j] += a[i]*b[j];
        }
    }

#pragma unroll
    for (int i=0;i<4;i++)
#pragma unroll
        for (int j=0;j<6;j++) acc[i][j] += bias[n0+j];

    if (pa.l2n[mi]) {
        __syncthreads();
#pragma unroll
        for (int i=0;i<4;i++) {
            float ss = 0.f;
#pragma unroll
            for (int j=0;j<6;j++) ss += acc[i][j]*acc[i][j];
            Xs[(m0+i)*17 + tn] = ss;
        }
        __syncthreads();
        if (tid < 64) {
            float s = 0.f;
#pragma unroll
            for (int t=0;t<16;t++) s += Xs[tid*17+t];
            Ws[tid] = 1.f / fmaxf(sqrtf(s), 1e-6f);
        }
        __syncthreads();
#pragma unroll
        for (int i=0;i<4;i++) {
            float sc = Ws[m0+i];
#pragma unroll
            for (int j=0;j<6;j++) acc[i][j] *= sc;
        }
    }

    int mode = pa.mode[mi];
    if (mode) {
        int perlen = (mode==1) ? 128 : 196;
        __nv_bfloat16* hiB = (__nv_bfloat16*)pa.Out[mi];
        __nv_bfloat16* loB = (__nv_bfloat16*)pa.Out2[mi];
#pragma unroll
        for (int i=0;i<4;i++) {
            int gr = tile*64 + m0 + i;
            int bb = gr / perlen, rr = gr - bb*perlen;
            long base = ((long)bb*perlen + rr)*H + n0;
#pragma unroll
            for (int j=0;j<6;j++) {
                float x = acc[i][j];
                __nv_bfloat16 hv = __float2bfloat16(x);
                __nv_bfloat16 lv = __float2bfloat16(x - __bfloat162float(hv));
                hiB[base+j] = hv;
                loB[base+j] = lv;
            }
        }
    } else {
        int L = pa.L[mi];
        if (L > 0) {
            float* O = pa.Out[mi];
#pragma unroll
            for (int i=0;i<4;i++) {
                int gr = tile*64 + m0 + i;
                int bb = gr / L, pp = gr - bb*L;
                float* base = O + (long)bb*H*L + pp;
#pragma unroll
                for (int j=0;j<6;j++) base[(n0+j)*L] = acc[i][j];
            }
        } else {
            float* O = pa.Out[mi] + (long)tile*64*H;
#pragma unroll
            for (int i=0;i<4;i++)
#pragma unroll
                for (int j=0;j<6;j++) O[(m0+i)*H + n0 + j] = acc[i][j];
        }
    }
}

// ---------------- K2: out[i,j] = 0.5*( t[i].d[j] + t[i].v[j] ) ----------------
__global__ void gg_kernel(float* __restrict__ out)
{
    int i = blockIdx.x, j = threadIdx.x;
    const float* ti = g_t + i*H;
    const float* dj = g_d + j*H;
    const float* vj = g_v + j*H;
    float s = 0.f;
#pragma unroll 8
    for (int h=0;h<H;h++) s += ti[h]*(dj[h]+vj[h]);
    out[i*64+j] = 0.5f*s;
}

// ---------------- K3: TGL via mma.sync, softmax in registers ----------------
// scores(128x128) = Q[b] @ K[c]^T (split bf16, 3 terms) -> in-reg row softmax
// -> column mean w[k] -> ctx = w.V[c] -> LN -> l2n -> dot d[b]; out += 0.5*val
#define TRP 104
#define TOFF_QHI 0
#define TOFF_QLO (TOFF_QHI + 128*TRP*2)
#define TOFF_KHI (TOFF_QLO + 128*TRP*2)
#define TOFF_KLO (TOFF_KHI + 128*TRP*2)
#define TOFF_CS  (TOFF_KLO + 128*TRP*2)      // colsum [8][128] f32
#define TOFF_WV  (TOFF_CS + 8*128*4)         // [128] f32
#define TOFF_CTX (TOFF_WV + 128*4)           // [96] f32
#define SM_TGL   (TOFF_CTX + 96*4 + 16)

__global__ __launch_bounds__(256,1) void tgl_mma(
    const float* __restrict__ lng, const float* __restrict__ lnb,
    float* __restrict__ out)
{
    extern __shared__ char smem[];
    uint32_t sb = smem_u32(smem);
    int tid = threadIdx.x;
    int wid = tid >> 5, lane = tid & 31;
    int b = blockIdx.y, c = blockIdx.x;

    // ---- load Q/K hi+lo tiles (12 uint4 per row, stride 13 uint4) ----
    {
        const uint4* Qh = (const uint4*)(g_Qhi + (long)b*QLEN*H);
        const uint4* Ql = (const uint4*)(g_Qlo + (long)b*QLEN*H);
        const uint4* Kh = (const uint4*)(g_Khi + (long)c*QLEN*H);
        const uint4* Kl = (const uint4*)(g_Klo + (long)c*QLEN*H);
        uint4* dQh = (uint4*)(smem + TOFF_QHI);
        uint4* dQl = (uint4*)(smem + TOFF_QLO);
        uint4* dKh = (uint4*)(smem + TOFF_KHI);
        uint4* dKl = (uint4*)(smem + TOFF_KLO);
        for (int idx=tid; idx<128*12; idx+=256) {
            int r = idx/12, q = idx%12;
            dQh[r*13+q] = Qh[idx];
            dQl[r*13+q] = Ql[idx];
            dKh[r*13+q] = Kh[idx];
            dKl[r*13+q] = Kl[idx];
        }
    }
    __syncthreads();

    // ---- A (Q) fragments: warp's 16-row band, 6 k-steps, hi+lo ----
    int m0 = wid*16;
    uint32_t qhi[6][4], qlo[6][4];
    {
        int rrow = m0 + (lane & 7) + ((lane >> 3) & 1) * 8;
        int rchk = ((lane >> 4) & 1) * 16;
#pragma unroll
        for (int ks=0; ks<6; ks++) {
            ldsm_x4(qhi[ks], sb + TOFF_QHI + rrow*(TRP*2) + ks*32 + rchk);
            ldsm_x4(qlo[ks], sb + TOFF_QLO + rrow*(TRP*2) + ks*32 + rchk);
        }
    }

    // ---- GEMM: 16 n-tiles of 8 cols ----
    float acc[16][4];
    int brow = lane & 7;
    int bchk = ((lane >> 3) & 1) * 16;
#pragma unroll
    for (int nt=0; nt<16; nt++) {
        acc[nt][0]=0.f; acc[nt][1]=0.f; acc[nt][2]=0.f; acc[nt][3]=0.f;
        uint32_t bh_addr = sb + TOFF_KHI + (nt*8+brow)*(TRP*2) + bchk;
        uint32_t bl_addr = sb + TOFF_KLO + (nt*8+brow)*(TRP*2) + bchk;
#pragma unroll
        for (int ks=0; ks<6; ks++) {
            uint32_t kh[2], kl[2];
            ldsm_x2(kh, bh_addr + ks*32);
            ldsm_x2(kl, bl_addr + ks*32);
            mma16816(acc[nt], qhi[ks], kh);
            mma16816(acc[nt], qlo[ks], kh);
            mma16816(acc[nt], qhi[ks], kl);
        }
    }

    // ---- in-register row softmax ----
    // fragment rows: r1 = m0 + (lane>>2)  (d0,d1), r2 = r1+8 (d2,d3)
    // fragment cols: c = nt*8 + (lane&3)*2 + {0,1}
    const float SC = 0.1020620726159658f;   // 1/sqrt(96)
    float m1 = -1e30f, m2 = -1e30f;
#pragma unroll
    for (int nt=0; nt<16; nt++) {
        m1 = fmaxf(m1, fmaxf(acc[nt][0], acc[nt][1]));
        m2 = fmaxf(m2, fmaxf(acc[nt][2], acc[nt][3]));
    }
    m1 = fmaxf(m1, __shfl_xor_sync(0xffffffffu, m1, 1));
    m1 = fmaxf(m1, __shfl_xor_sync(0xffffffffu, m1, 2));
    m2 = fmaxf(m2, __shfl_xor_sync(0xffffffffu, m2, 1));
    m2 = fmaxf(m2, __shfl_xor_sync(0xffffffffu, m2, 2));

    float s1 = 0.f, s2 = 0.f;
#pragma unroll
    for (int nt=0; nt<16; nt++) {
        float e0 = __expf((acc[nt][0]-m1)*SC);
        float e1 = __expf((acc[nt][1]-m1)*SC);
        float e2 = __expf((acc[nt][2]-m2)*SC);
        float e3 = __expf((acc[nt][3]-m2)*SC);
        acc[nt][0]=e0; acc[nt][1]=e1; acc[nt][2]=e2; acc[nt][3]=e3;
        s1 += e0+e1; s2 += e2+e3;
    }
    s1 += __shfl_xor_sync(0xffffffffu, s1, 1);
    s1 += __shfl_xor_sync(0xffffffffu, s1, 2);
    s2 += __shfl_xor_sync(0xffffffffu, s2, 1);
    s2 += __shfl_xor_sync(0xffffffffu, s2, 2);
    float inv1 = 1.f/s1, inv2 = 1.f/s2;

    // ---- column partial sums over this warp's 16 rows ----
    float* colsum = (float*)(smem + TOFF_CS);
#pragma unroll
    for (int nt=0; nt<16; nt++) {
        float v0 = acc[nt][0]*inv1 + acc[nt][2]*inv2;
        float v1 = acc[nt][1]*inv1 + acc[nt][3]*inv2;
#pragma unroll
        for (int o=4; o<32; o<<=1) {
            v0 += __shfl_xor_sync(0xffffffffu, v0, o);
            v1 += __shfl_xor_sync(0xffffffffu, v1, o);
        }
        if (lane < 4) {
            colsum[wid*128 + nt*8 + lane*2]     = v0;
            colsum[wid*128 + nt*8 + lane*2 + 1] = v1;
        }
    }
    __syncthreads();

    // ---- w[k] = (1/128) sum over warps ----
    float* wv = (float*)(smem + TOFF_WV);
    if (tid < 128) {
        float s = 0.f;
#pragma unroll
        for (int w=0; w<8; w++) s += colsum[w*128 + tid];
        wv[tid] = s * (1.f/128.f);
    }
    __syncthreads();

    // ---- context[h] = sum_k w[k]*V_t[h][k] ----
    float* ctxs = (float*)(smem + TOFF_CTX);
    if (tid < 96) {
        const float* Vr = g_Vt + (long)c*H*QLEN + tid*QLEN;
        float s = 0.f;
#pragma unroll
        for (int k4=0;k4<QLEN/4;k4++) {
            float4 v = ((const float4*)Vr)[k4];
            s += wv[k4*4]*v.x + wv[k4*4+1]*v.y + wv[k4*4+2]*v.z + wv[k4*4+3]*v.w;
        }
        ctxs[tid] = s;
    }
    __syncthreads();

    // ---- LayerNorm + l2n + dot(d[b]) on warp 0 ----
    if (tid < 32) {
        float x0=ctxs[tid], x1=ctxs[tid+32], x2=ctxs[tid+64];
        float mu = x0+x1+x2;
#pragma unroll
        for (int o=16;o;o>>=1) mu += __shfl_xor_sync(0xffffffffu,mu,o);
        mu *= (1.f/96.f);
        float d0=x0-mu, d1=x1-mu, d2=x2-mu;
        float var = d0*d0 + d1*d1 + d2*d2;
#pragma unroll
        for (int o=16;o;o>>=1) var += __shfl_xor_sync(0xffffffffu,var,o);
        var *= (1.f/96.f);
        float rstd = rsqrtf(var + 1e-5f);
        float n0v = d0*rstd*lng[tid]    + lnb[tid];
        float n1v = d1*rstd*lng[tid+32] + lnb[tid+32];
        float n2v = d2*rstd*lng[tid+64] + lnb[tid+64];
        float ss = n0v*n0v + n1v*n1v + n2v*n2v;
#pragma unroll
        for (int o=16;o;o>>=1) ss += __shfl_xor_sync(0xffffffffu,ss,o);
        float sc = 1.f / fmaxf(sqrtf(ss), 1e-6f);
        const float* db = g_d + b*H;
        float dt = db[tid]*n0v + db[tid+32]*n1v + db[tid+64]*n2v;
#pragma unroll
        for (int o=16;o;o>>=1) dt += __shfl_xor_sync(0xffffffffu,dt,o);
        if (tid==0) out[b*64+c] += 0.5f * (dt*sc);
    }
}

// ---------------- K4: CLL via mma.sync bf16 split-precision ----------------
#define RPAD 104
#define OFF_AHI 0
#define OFF_ALO (OFF_AHI + 128*RPAD*2)
#define OFF_BHI (OFF_ALO + 128*RPAD*2)
#define OFF_BLO (OFF_BHI + 200*RPAD*2)
#define OFF_RED (OFF_BLO + 200*RPAD*2)
#define SM_CLL  (OFF_RED + 64)

__global__ __launch_bounds__(256,1) void cll_mma(float* __restrict__ out)
{
    extern __shared__ char smem[];
    uint32_t sb = smem_u32(smem);
    int tid = threadIdx.x;
    int wid = tid >> 5, lane = tid & 31;
    int b = blockIdx.y, c = blockIdx.x;

    {
        const uint4* Ah = (const uint4*)(g_Ahi + (long)b*QLEN*H);
        const uint4* Al = (const uint4*)(g_Alo + (long)b*QLEN*H);
        uint4* dAh = (uint4*)(smem + OFF_AHI);
        uint4* dAl = (uint4*)(smem + OFF_ALO);
        for (int idx=tid; idx<128*12; idx+=256) {
            int r = idx/12, q = idx%12;
            dAh[r*13+q] = Ah[idx];
            dAl[r*13+q] = Al[idx];
        }
        const uint4* Bh = (const uint4*)(g_Bhi + (long)c*PLEN*H);
        const uint4* Bl = (const uint4*)(g_Blo + (long)c*PLEN*H);
        uint4* dBh = (uint4*)(smem + OFF_BHI);
        uint4* dBl = (uint4*)(smem + OFF_BLO);
        for (int idx=tid; idx<196*12; idx+=256) {
            int r = idx/12, q = idx%12;
            dBh[r*13+q] = Bh[idx];
            dBl[r*13+q] = Bl[idx];
        }
        uint4 z = make_uint4(0,0,0,0);
        for (int idx=tid; idx<4*13; idx+=256) {
            int r = 196 + idx/13, q = idx%13;
            dBh[r*13+q] = z;
            dBl[r*13+q] = z;
        }
    }
    __syncthreads();

    int m0 = wid*16;
    uint32_t ahi[6][4], alo[6][4];
    {
        int rrow = m0 + (lane & 7) + ((lane >> 3) & 1) * 8;
        int rchk = ((lane >> 4) & 1) * 16;
#pragma unroll
        for (int ks=0; ks<6; ks++) {
            ldsm_x4(ahi[ks], sb + OFF_AHI + rrow*(RPAD*2) + ks*32 + rchk);
            ldsm_x4(alo[ks], sb + OFF_ALO + rrow*(RPAD*2) + ks*32 + rchk);
        }
    }

    float mbest = -1e30f;
    int brow = lane & 7;
    int bchk = ((lane >> 3) & 1) * 16;
    for (int nt=0; nt<25; nt++) {
        float acc[4] = {0.f, 0.f, 0.f, 0.f};
        int n0 = nt*8;
        uint32_t baddr_h = sb + OFF_BHI + (n0+brow)*(RPAD*2) + bchk;
        uint32_t baddr_l = sb + OFF_BLO + (n0+brow)*(RPAD*2) + bchk;
#pragma unroll
        for (int ks=0; ks<6; ks++) {
            uint32_t bh[2], bl[2];
            ldsm_x2(bh, baddr_h + ks*32);
            ldsm_x2(bl, baddr_l + ks*32);
            mma16816(acc, ahi[ks], bh);
            mma16816(acc, alo[ks], bh);
            mma16816(acc, ahi[ks], bl);
        }
        int col0 = n0 + (lane & 3)*2;
        if (col0 < PLEN)   mbest = fmaxf(mbest, fmaxf(acc[0], acc[2]));
        if (col0+1 < PLEN) mbest = fmaxf(mbest, fmaxf(acc[1], acc[3]));
    }

#pragma unroll
    for (int o=16;o;o>>=1) mbest = fmaxf(mbest, __shfl_xor_sync(0xffffffffu,mbest,o));
    float* red = (float*)(smem + OFF_RED);
    if (lane == 0) red[wid] = mbest;
    __syncthreads();
    if (tid == 0) {
        float m = red[0];
#pragma unroll
        for (int w=1;w<8;w++) m = fmaxf(m, red[w]);
        out[b*64+c] += 0.5f*m;
    }
}

// ---------------- host ----------------
extern "C" void kernel_launch(void* const* d_in, const int* in_sizes, int n_in,
                              void* d_out, int out_size)
{
    const float* z_d_cls = (const float*)d_in[0];
    const float* Z_d_tok = (const float*)d_in[1];
    const float* z_t_cls = (const float*)d_in[2];
    const float* Z_t_tok = (const float*)d_in[3];
    const float* z_v_cls = (const float*)d_in[4];
    const float* Z_v_pat = (const float*)d_in[5];
    const float *W_t_cls=(const float*)d_in[6],  *b_t_cls=(const float*)d_in[7];
    const float *W_d_cls=(const float*)d_in[8],  *b_d_cls=(const float*)d_in[9];
    const float *W_v_cls=(const float*)d_in[10], *b_v_cls=(const float*)d_in[11];
    const float *W_t_tok=(const float*)d_in[12], *b_t_tok=(const float*)d_in[13];
    const float *W_v_pat=(const float*)d_in[14], *b_v_pat=(const float*)d_in[15];
    const float *W_q=(const float*)d_in[16], *b_q=(const float*)d_in[17];
    const float *W_k=(const float*)d_in[18], *b_k=(const float*)d_in[19];
    const float *W_v=(const float*)d_in[20], *b_v=(const float*)d_in[21];
    const float *ln_g=(const float*)d_in[22], *ln_b=(const float*)d_in[23];
    float* out = (float*)d_out;

    float *Vp,*tp,*dp,*vp;
    void *qhi,*qlo,*khi,*klo,*ahi,*alo,*bhi,*blo;
    cudaGetSymbolAddress((void**)&Vp,  g_Vt);
    cudaGetSymbolAddress((void**)&tp,  g_t);
    cudaGetSymbolAddress((void**)&dp,  g_d);
    cudaGetSymbolAddress((void**)&vp,  g_v);
    cudaGetSymbolAddress(&qhi, g_Qhi);
    cudaGetSymbolAddress(&qlo, g_Qlo);
    cudaGetSymbolAddress(&khi, g_Khi);
    cudaGetSymbolAddress(&klo, g_Klo);
    cudaGetSymbolAddress(&ahi, g_Ahi);
    cudaGetSymbolAddress(&alo, g_Alo);
    cudaGetSymbolAddress(&bhi, g_Bhi);
    cudaGetSymbolAddress(&blo, g_Blo);

    cudaFuncSetAttribute(tgl_mma, cudaFuncAttributeMaxDynamicSharedMemorySize, SM_TGL);
    cudaFuncSetAttribute(cll_mma, cudaFuncAttributeMaxDynamicSharedMemorySize, SM_CLL);

    ProjArgs pa;
    for (int i=0;i<8;i++) { pa.Out2[i]=nullptr; pa.mode[i]=0; pa.L[i]=0; pa.l2n[i]=0; }
    pa.X[0]=Z_d_tok; pa.W[0]=W_q;     pa.Bv[0]=b_q;     pa.Out[0]=(float*)qhi; pa.Out2[0]=qlo; pa.mode[0]=1;
    pa.X[1]=Z_t_tok; pa.W[1]=W_k;     pa.Bv[1]=b_k;     pa.Out[1]=(float*)khi; pa.Out2[1]=klo; pa.mode[1]=1;
    pa.X[2]=Z_t_tok; pa.W[2]=W_v;     pa.Bv[2]=b_v;     pa.Out[2]=Vp;  pa.L[2]=QLEN;
    pa.X[3]=Z_t_tok; pa.W[3]=W_t_tok; pa.Bv[3]=b_t_tok; pa.Out[3]=(float*)ahi; pa.Out2[3]=alo; pa.l2n[3]=1; pa.mode[3]=1;
    pa.X[4]=Z_v_pat; pa.W[4]=W_v_pat; pa.Bv[4]=b_v_pat; pa.Out[4]=(float*)bhi; pa.Out2[4]=blo; pa.l2n[4]=1; pa.mode[4]=2;
    pa.X[5]=z_t_cls; pa.W[5]=W_t_cls; pa.Bv[5]=b_t_cls; pa.Out[5]=tp;  pa.l2n[5]=1;
    pa.X[6]=z_d_cls; pa.W[6]=W_d_cls; pa.Bv[6]=b_d_cls; pa.Out[6]=dp;  pa.l2n[6]=1;
    pa.X[7]=z_v_cls; pa.W[7]=W_v_cls; pa.Bv[7]=b_v_cls; pa.Out[7]=vp;  pa.l2n[7]=1;
    int nt[8] = {128,128,128,128,196,1,1,1};
    pa.tile_start[0]=0;
    for (int i=0;i<8;i++) pa.tile_start[i+1]=pa.tile_start[i]+nt[i];

    proj_all<<<pa.tile_start[8],256>>>(pa);

    // out = 0.5*(S_TGG + S_CGG)
    gg_kernel<<<64,64>>>(out);
    // out += 0.5*S_TGL  (mma.sync bf16 split, in-reg softmax)
    tgl_mma<<<dim3(64,64),256,SM_TGL>>>(ln_g, ln_b, out);
    // out += 0.5*S_CLL  (mma.sync bf16 split)
    cll_mma<<<dim3(64,64),256,SM_CLL>>>(out);
}